// round 11
// baseline (speedup 1.0000x reference)
#include <cuda_runtime.h>
#include <stdint.h>

#define NODES 50000
#define EDGES 800000
#define DD    128
#define EPS   1e-5f

// ---------------- scratch (static device globals; no allocation) ----------------
__device__ float g_agg[(size_t)NODES * DD];
__device__ float g_h1[(size_t)NODES * DD];   // raw pre-BN layer-0 output
__device__ float g_h2[(size_t)NODES * DD];   // raw pre-BN layer-1 output
__device__ float g_rdeg[NODES];
__device__ int   g_deg[NODES];
__device__ int   g_csr_ptr[NODES + 1];
__device__ int   g_cursor[NODES];
__device__ int   g_csr_src[EDGES];
__device__ int   g_bsum[256];
__device__ int   g_boff[256];
__device__ float g_stats[2 * DD];            // col sums / sumsq (reset by finalize)
__device__ float g_sc[DD];                   // lazy-BN scale per column
__device__ float g_sh[DD];                   // lazy-BN shift per column

// ---------------- degree + CSR build ----------------
__global__ void k_count_deg(const int* __restrict__ dst, int e) {
    int i = blockIdx.x * blockDim.x + threadIdx.x;
    if (i < e) atomicAdd(&g_deg[dst[i]], 1);
}

__global__ void k_scan1(int n) {
    __shared__ int s[256];
    int tid = threadIdx.x;
    int i = blockIdx.x * 256 + tid;
    int v = (i < n) ? g_deg[i] : 0;
    s[tid] = v;
    __syncthreads();
#pragma unroll
    for (int o = 1; o < 256; o <<= 1) {
        int x = (tid >= o) ? s[tid - o] : 0;
        __syncthreads();
        s[tid] += x;
        __syncthreads();
    }
    if (i < n) g_csr_ptr[i] = s[tid] - v;
    if (tid == 255) g_bsum[blockIdx.x] = s[255];
}

__global__ void k_scan2(int nb) {
    __shared__ int s[256];
    int tid = threadIdx.x;
    int v = (tid < nb) ? g_bsum[tid] : 0;
    s[tid] = v;
    __syncthreads();
#pragma unroll
    for (int o = 1; o < 256; o <<= 1) {
        int x = (tid >= o) ? s[tid - o] : 0;
        __syncthreads();
        s[tid] += x;
        __syncthreads();
    }
    if (tid < nb) g_boff[tid] = s[tid] - v;
}

__global__ void k_scan3(int n, int e) {
    int i = blockIdx.x * blockDim.x + threadIdx.x;
    if (i < n) {
        int p = g_csr_ptr[i] + g_boff[blockIdx.x];
        g_csr_ptr[i] = p;
        g_cursor[i] = p;
        int d = g_deg[i];
        g_rdeg[i] = 1.0f / (float)(d > 0 ? d : 1);
    }
    if (i == 0) g_csr_ptr[n] = e;
}

__global__ void k_fill(const int* __restrict__ src, const int* __restrict__ dst, int e) {
    int i = blockIdx.x * blockDim.x + threadIdx.x;
    if (i < e) {
        int pos = atomicAdd(&g_cursor[dst[i]], 1);
        g_csr_src[pos] = src[i];
    }
}

// ---------------- gather: one warp per dst node; lazy BN+ReLU on input ----------------
template<bool BN>
__global__ __launch_bounds__(256)
void k_gather(const float* __restrict__ h, int n) {
    int node = (blockIdx.x * blockDim.x + threadIdx.x) >> 5;
    int lane = threadIdx.x & 31;
    if (node >= n) return;
    float4 sc, sh;
    if (BN) {
        sc = *reinterpret_cast<const float4*>(g_sc + lane * 4);
        sh = *reinterpret_cast<const float4*>(g_sh + lane * 4);
    }
    int beg = g_csr_ptr[node];
    int end = g_csr_ptr[node + 1];
    float4 acc = make_float4(0.f, 0.f, 0.f, 0.f);
    for (int base = beg; base < end; base += 32) {
        int mye  = base + lane;
        int sidx = (mye < end) ? g_csr_src[mye] : 0;
        int cnt  = min(32, end - base);
        int j = 0;
        for (; j + 3 < cnt; j += 4) {
            int s0 = __shfl_sync(0xffffffffu, sidx, j);
            int s1 = __shfl_sync(0xffffffffu, sidx, j + 1);
            int s2 = __shfl_sync(0xffffffffu, sidx, j + 2);
            int s3 = __shfl_sync(0xffffffffu, sidx, j + 3);
            float4 v0 = *reinterpret_cast<const float4*>(h + (size_t)s0 * DD + lane * 4);
            float4 v1 = *reinterpret_cast<const float4*>(h + (size_t)s1 * DD + lane * 4);
            float4 v2 = *reinterpret_cast<const float4*>(h + (size_t)s2 * DD + lane * 4);
            float4 v3 = *reinterpret_cast<const float4*>(h + (size_t)s3 * DD + lane * 4);
            if (BN) {
                v0.x = fmaxf(fmaf(v0.x, sc.x, sh.x), 0.f);
                v0.y = fmaxf(fmaf(v0.y, sc.y, sh.y), 0.f);
                v0.z = fmaxf(fmaf(v0.z, sc.z, sh.z), 0.f);
                v0.w = fmaxf(fmaf(v0.w, sc.w, sh.w), 0.f);
                v1.x = fmaxf(fmaf(v1.x, sc.x, sh.x), 0.f);
                v1.y = fmaxf(fmaf(v1.y, sc.y, sh.y), 0.f);
                v1.z = fmaxf(fmaf(v1.z, sc.z, sh.z), 0.f);
                v1.w = fmaxf(fmaf(v1.w, sc.w, sh.w), 0.f);
                v2.x = fmaxf(fmaf(v2.x, sc.x, sh.x), 0.f);
                v2.y = fmaxf(fmaf(v2.y, sc.y, sh.y), 0.f);
                v2.z = fmaxf(fmaf(v2.z, sc.z, sh.z), 0.f);
                v2.w = fmaxf(fmaf(v2.w, sc.w, sh.w), 0.f);
                v3.x = fmaxf(fmaf(v3.x, sc.x, sh.x), 0.f);
                v3.y = fmaxf(fmaf(v3.y, sc.y, sh.y), 0.f);
                v3.z = fmaxf(fmaf(v3.z, sc.z, sh.z), 0.f);
                v3.w = fmaxf(fmaf(v3.w, sc.w, sh.w), 0.f);
            }
            acc.x += v0.x + v1.x + v2.x + v3.x;
            acc.y += v0.y + v1.y + v2.y + v3.y;
            acc.z += v0.z + v1.z + v2.z + v3.z;
            acc.w += v0.w + v1.w + v2.w + v3.w;
        }
        for (; j < cnt; j++) {
            int s0 = __shfl_sync(0xffffffffu, sidx, j);
            float4 v0 = *reinterpret_cast<const float4*>(h + (size_t)s0 * DD + lane * 4);
            if (BN) {
                v0.x = fmaxf(fmaf(v0.x, sc.x, sh.x), 0.f);
                v0.y = fmaxf(fmaf(v0.y, sc.y, sh.y), 0.f);
                v0.z = fmaxf(fmaf(v0.z, sc.z, sh.z), 0.f);
                v0.w = fmaxf(fmaf(v0.w, sc.w, sh.w), 0.f);
            }
            acc.x += v0.x; acc.y += v0.y; acc.z += v0.z; acc.w += v0.w;
        }
    }
    float rd = g_rdeg[node];
    acc.x *= rd; acc.y *= rd; acc.z *= rd; acc.w *= rd;
    *reinterpret_cast<float4*>(g_agg + (size_t)node * DD + lane * 4) = acc;
}

// ---------------- tf32 tensor-core dual GEMM + bias + residual (+stats) ----------
__device__ __forceinline__ uint32_t f2tf32(float x) {
    uint32_t r;
    asm("cvt.rna.tf32.f32 %0, %1;" : "=r"(r) : "f"(x));
    return r;
}

__device__ __forceinline__ void mma_tf32(float* d, const uint32_t* a, const uint32_t* b) {
    asm volatile(
        "mma.sync.aligned.m16n8k8.row.col.f32.tf32.tf32.f32 "
        "{%0,%1,%2,%3}, {%4,%5,%6,%7}, {%8,%9}, {%0,%1,%2,%3};\n"
        : "+f"(d[0]), "+f"(d[1]), "+f"(d[2]), "+f"(d[3])
        : "r"(a[0]), "r"(a[1]), "r"(a[2]), "r"(a[3]), "r"(b[0]), "r"(b[1]));
}

#define BM 128
#define BK 16
#define A_STRIDE 20
#define B_STRIDE 136

// BNIN: input h is raw pre-BN -> apply max(x*sc+sh,0) at every read of h.
// DO_STATS: accumulate column sum/sumsq of the raw output into g_stats.
template<bool BNIN, bool DO_STATS>
__global__ __launch_bounds__(256, 2)
void k_gemm_tc(const float* __restrict__ h,
               const float* __restrict__ Ws, const float* __restrict__ Wn,
               const float* __restrict__ bias, float* __restrict__ out, int nrows) {
    __shared__ uint32_t Ah[128][A_STRIDE];
    __shared__ uint32_t Aa[128][A_STRIDE];
    __shared__ uint32_t Bs[BK][B_STRIDE];
    __shared__ uint32_t Bn[BK][B_STRIDE];
    __shared__ float s_sum[DD];
    __shared__ float s_sq[DD];

    const int tid  = threadIdx.x;
    const int warp = tid >> 5;
    const int lane = tid & 31;
    const int g    = lane >> 2;
    const int t    = lane & 3;
    const int wm   = warp & 3;
    const int wn   = warp >> 2;
    const int m0   = blockIdx.x * BM;
    const int wrow = wm * 32;
    const int wcol = wn * 64;

    if (DO_STATS && tid < DD) { s_sum[tid] = 0.f; s_sq[tid] = 0.f; }

    float acc[2][8][4];
#pragma unroll
    for (int mt = 0; mt < 2; mt++)
#pragma unroll
        for (int nt = 0; nt < 8; nt++)
#pragma unroll
            for (int j = 0; j < 4; j++) acc[mt][nt][j] = 0.f;

    for (int kc = 0; kc < DD / BK; kc++) {
        const int ks = kc * BK;
#pragma unroll
        for (int r = 0; r < 2; r++) {
            int id  = tid + r * 256;
            int row = id >> 2;
            int c4  = id & 3;
            int grow = m0 + row;
            float4 vh = make_float4(0.f, 0.f, 0.f, 0.f);
            float4 va = make_float4(0.f, 0.f, 0.f, 0.f);
            if (grow < nrows) {
                size_t off = (size_t)grow * DD + ks + c4 * 4;
                vh = *reinterpret_cast<const float4*>(h + off);
                va = *reinterpret_cast<const float4*>(g_agg + off);
                if (BNIN) {
                    float4 s4 = *reinterpret_cast<const float4*>(g_sc + ks + c4 * 4);
                    float4 h4 = *reinterpret_cast<const float4*>(g_sh + ks + c4 * 4);
                    vh.x = fmaxf(fmaf(vh.x, s4.x, h4.x), 0.f);
                    vh.y = fmaxf(fmaf(vh.y, s4.y, h4.y), 0.f);
                    vh.z = fmaxf(fmaf(vh.z, s4.z, h4.z), 0.f);
                    vh.w = fmaxf(fmaf(vh.w, s4.w, h4.w), 0.f);
                }
            }
            uint4 ph = make_uint4(f2tf32(vh.x), f2tf32(vh.y), f2tf32(vh.z), f2tf32(vh.w));
            uint4 pa = make_uint4(f2tf32(va.x), f2tf32(va.y), f2tf32(va.z), f2tf32(va.w));
            *reinterpret_cast<uint4*>(&Ah[row][c4 * 4]) = ph;
            *reinterpret_cast<uint4*>(&Aa[row][c4 * 4]) = pa;
        }
#pragma unroll
        for (int r = 0; r < 2; r++) {
            int id  = tid + r * 256;
            int row = id >> 5;
            int c4  = id & 31;
            size_t off = (size_t)(ks + row) * DD + c4 * 4;
            float4 vs = *reinterpret_cast<const float4*>(Ws + off);
            float4 vn = *reinterpret_cast<const float4*>(Wn + off);
            uint4 ps = make_uint4(f2tf32(vs.x), f2tf32(vs.y), f2tf32(vs.z), f2tf32(vs.w));
            uint4 pn = make_uint4(f2tf32(vn.x), f2tf32(vn.y), f2tf32(vn.z), f2tf32(vn.w));
            *reinterpret_cast<uint4*>(&Bs[row][c4 * 4]) = ps;
            *reinterpret_cast<uint4*>(&Bn[row][c4 * 4]) = pn;
        }
        __syncthreads();

#pragma unroll
        for (int ks8 = 0; ks8 < BK / 8; ks8++) {
            const int kb = ks8 * 8;
            uint32_t a[2][4], b[8][2];
#pragma unroll
            for (int mt = 0; mt < 2; mt++) {
                int r = wrow + mt * 16;
                a[mt][0] = Ah[r + g][kb + t];
                a[mt][1] = Ah[r + g + 8][kb + t];
                a[mt][2] = Ah[r + g][kb + t + 4];
                a[mt][3] = Ah[r + g + 8][kb + t + 4];
            }
#pragma unroll
            for (int nt = 0; nt < 8; nt++) {
                int c = wcol + nt * 8 + g;
                b[nt][0] = Bs[kb + t][c];
                b[nt][1] = Bs[kb + t + 4][c];
            }
#pragma unroll
            for (int mt = 0; mt < 2; mt++)
#pragma unroll
                for (int nt = 0; nt < 8; nt++)
                    mma_tf32(acc[mt][nt], a[mt], b[nt]);
#pragma unroll
            for (int mt = 0; mt < 2; mt++) {
                int r = wrow + mt * 16;
                a[mt][0] = Aa[r + g][kb + t];
                a[mt][1] = Aa[r + g + 8][kb + t];
                a[mt][2] = Aa[r + g][kb + t + 4];
                a[mt][3] = Aa[r + g + 8][kb + t + 4];
            }
#pragma unroll
            for (int nt = 0; nt < 8; nt++) {
                int c = wcol + nt * 8 + g;
                b[nt][0] = Bn[kb + t][c];
                b[nt][1] = Bn[kb + t + 4][c];
            }
#pragma unroll
            for (int mt = 0; mt < 2; mt++)
#pragma unroll
                for (int nt = 0; nt < 8; nt++)
                    mma_tf32(acc[mt][nt], a[mt], b[nt]);
        }
        __syncthreads();
    }

    // epilogue: + bias + residual (BN(h) when BNIN), write raw out, accumulate stats
#pragma unroll
    for (int mt = 0; mt < 2; mt++) {
#pragma unroll
        for (int rr = 0; rr < 2; rr++) {
            int grow = m0 + wrow + mt * 16 + g + rr * 8;
            if (grow < nrows) {
#pragma unroll
                for (int nt = 0; nt < 8; nt++) {
                    int col = wcol + nt * 8 + t * 2;
                    size_t off = (size_t)grow * DD + col;
                    float2 res = *reinterpret_cast<const float2*>(h + off);
                    if (BNIN) {
                        float2 s2 = *reinterpret_cast<const float2*>(g_sc + col);
                        float2 h2 = *reinterpret_cast<const float2*>(g_sh + col);
                        res.x = fmaxf(fmaf(res.x, s2.x, h2.x), 0.f);
                        res.y = fmaxf(fmaf(res.y, s2.y, h2.y), 0.f);
                    }
                    float2 bv = *reinterpret_cast<const float2*>(bias + col);
                    float2 o;
                    o.x = acc[mt][nt][rr * 2 + 0] + bv.x + res.x;
                    o.y = acc[mt][nt][rr * 2 + 1] + bv.y + res.y;
                    *reinterpret_cast<float2*>(out + off) = o;
                    if (DO_STATS) {
                        atomicAdd(&s_sum[col],     o.x);
                        atomicAdd(&s_sum[col + 1], o.y);
                        atomicAdd(&s_sq[col],      o.x * o.x);
                        atomicAdd(&s_sq[col + 1],  o.y * o.y);
                    }
                }
            }
        }
    }
    if (DO_STATS) {
        __syncthreads();
        if (tid < DD) {
            atomicAdd(&g_stats[tid],      s_sum[tid]);
            atomicAdd(&g_stats[DD + tid], s_sq[tid]);
        }
    }
}

// ---------------- finalize: stats -> (sc, sh), reset stats ----------------
__global__ void k_finalize(const float* __restrict__ gamma, const float* __restrict__ beta,
                           float n) {
    int i = threadIdx.x;
    if (i < DD) {
        float inv = 1.0f / n;
        float mu  = g_stats[i] * inv;
        float var = g_stats[DD + i] * inv - mu * mu;
        float scv = rsqrtf(var + EPS) * gamma[i];
        g_sc[i] = scv;
        g_sh[i] = beta[i] - mu * scv;
        g_stats[i] = 0.f;
        g_stats[DD + i] = 0.f;
    }
}

// ---------------- launch ----------------
extern "C" void kernel_launch(void* const* d_in, const int* in_sizes, int n_in,
                              void* d_out, int out_size) {
    const float* feat   = (const float*)d_in[0];
    const int*   src    = (const int*)d_in[1];
    const int*   dst    = (const int*)d_in[2];
    const float* Wself  = (const float*)d_in[3];
    const float* Wneigh = (const float*)d_in[4];
    const float* bias   = (const float*)d_in[5];
    const float* gamma  = (const float*)d_in[6];
    const float* beta   = (const float*)d_in[7];
    float* out = (float*)d_out;

    const int N = in_sizes[0] / DD;
    const int E = in_sizes[1];

    void *p_deg, *p_stats, *p_h1, *p_h2;
    cudaGetSymbolAddress(&p_deg, g_deg);
    cudaGetSymbolAddress(&p_stats, g_stats);
    cudaGetSymbolAddress(&p_h1, g_h1);
    cudaGetSymbolAddress(&p_h2, g_h2);

    // ---- CSR build ----
    const int nb = (N + 255) / 256;
    cudaMemsetAsync(p_deg, 0, (size_t)N * sizeof(int), 0);
    cudaMemsetAsync(p_stats, 0, 2 * DD * sizeof(float), 0);
    k_count_deg<<<(E + 255) / 256, 256>>>(dst, E);
    k_scan1<<<nb, 256>>>(N);
    k_scan2<<<1, 256>>>(nb);
    k_scan3<<<nb, 256>>>(N, E);
    k_fill<<<(E + 255) / 256, 256>>>(src, dst, E);

    const int gemm_blocks   = (N + BM - 1) / BM;
    const int gather_blocks = (N + 7) / 8;       // warp per node, 8 warps/block

    const float* raw_in[3]  = {feat, (const float*)p_h1, (const float*)p_h2};
    float*       raw_out[3] = {(float*)p_h1, (float*)p_h2, out};

    for (int l = 0; l < 3; l++) {
        const float* Ws = Wself + (size_t)l * DD * DD;
        const float* Wn = Wneigh + (size_t)l * DD * DD;
        const float* bl = bias + (size_t)l * DD;
        const float* hin = raw_in[l];
        float* ho = raw_out[l];

        if (l == 0) k_gather<false><<<gather_blocks, 256>>>(hin, N);
        else        k_gather<true ><<<gather_blocks, 256>>>(hin, N);

        if (l == 0)      k_gemm_tc<false, true ><<<gemm_blocks, 256>>>(hin, Ws, Wn, bl, ho, N);
        else if (l == 1) k_gemm_tc<true,  true ><<<gemm_blocks, 256>>>(hin, Ws, Wn, bl, ho, N);
        else             k_gemm_tc<true,  false><<<gemm_blocks, 256>>>(hin, Ws, Wn, bl, ho, N);

        if (l < 2)
            k_finalize<<<1, 128>>>(gamma + (size_t)l * DD, beta + (size_t)l * DD, (float)N);
    }
    (void)n_in; (void)out_size;
}

// round 12
// speedup vs baseline: 1.6190x; 1.6190x over previous
#include <cuda_runtime.h>
#include <stdint.h>

#define NODES 50000
#define EDGES 800000
#define DD    128
#define EPS   1e-5f

// ---------------- scratch (static device globals; no allocation) ----------------
__device__ float g_agg[(size_t)NODES * DD];
__device__ float g_h1[(size_t)NODES * DD];   // raw pre-BN layer-0 output
__device__ float g_h2[(size_t)NODES * DD];   // raw pre-BN layer-1 output
__device__ float g_rdeg[NODES];
__device__ int   g_deg[NODES];
__device__ int   g_csr_ptr[NODES + 1];
__device__ int   g_cursor[NODES];
__device__ int   g_csr_src[EDGES];
__device__ int   g_bsum[256];
__device__ int   g_boff[256];
__device__ float g_stats[2 * DD];            // col sums / sumsq (reset by finalize)
__device__ float g_sc[DD];                   // lazy-BN scale per column
__device__ float g_sh[DD];                   // lazy-BN shift per column

// ---------------- degree + CSR build ----------------
__global__ void k_count_deg(const int* __restrict__ dst, int e) {
    int i = blockIdx.x * blockDim.x + threadIdx.x;
    if (i < e) atomicAdd(&g_deg[dst[i]], 1);
}

__global__ void k_scan1(int n) {
    __shared__ int s[256];
    int tid = threadIdx.x;
    int i = blockIdx.x * 256 + tid;
    int v = (i < n) ? g_deg[i] : 0;
    s[tid] = v;
    __syncthreads();
#pragma unroll
    for (int o = 1; o < 256; o <<= 1) {
        int x = (tid >= o) ? s[tid - o] : 0;
        __syncthreads();
        s[tid] += x;
        __syncthreads();
    }
    if (i < n) g_csr_ptr[i] = s[tid] - v;
    if (tid == 255) g_bsum[blockIdx.x] = s[255];
}

__global__ void k_scan2(int nb) {
    __shared__ int s[256];
    int tid = threadIdx.x;
    int v = (tid < nb) ? g_bsum[tid] : 0;
    s[tid] = v;
    __syncthreads();
#pragma unroll
    for (int o = 1; o < 256; o <<= 1) {
        int x = (tid >= o) ? s[tid - o] : 0;
        __syncthreads();
        s[tid] += x;
        __syncthreads();
    }
    if (tid < nb) g_boff[tid] = s[tid] - v;
}

__global__ void k_scan3(int n, int e) {
    int i = blockIdx.x * blockDim.x + threadIdx.x;
    if (i < n) {
        int p = g_csr_ptr[i] + g_boff[blockIdx.x];
        g_csr_ptr[i] = p;
        g_cursor[i] = p;
        int d = g_deg[i];
        g_rdeg[i] = 1.0f / (float)(d > 0 ? d : 1);
    }
    if (i == 0) g_csr_ptr[n] = e;
}

__global__ void k_fill(const int* __restrict__ src, const int* __restrict__ dst, int e) {
    int i = blockIdx.x * blockDim.x + threadIdx.x;
    if (i < e) {
        int pos = atomicAdd(&g_cursor[dst[i]], 1);
        g_csr_src[pos] = src[i];
    }
}

// ---------------- gather: one warp per dst node; lazy BN+ReLU on input ------------
template<bool BN>
__global__ __launch_bounds__(256)
void k_gather(const float* __restrict__ h, int n) {
    int node = (blockIdx.x * blockDim.x + threadIdx.x) >> 5;
    int lane = threadIdx.x & 31;
    if (node >= n) return;
    float4 sc, sh;
    if (BN) {
        sc = *reinterpret_cast<const float4*>(g_sc + lane * 4);
        sh = *reinterpret_cast<const float4*>(g_sh + lane * 4);
    }
    int beg = g_csr_ptr[node];
    int end = g_csr_ptr[node + 1];
    float4 acc = make_float4(0.f, 0.f, 0.f, 0.f);
    for (int base = beg; base < end; base += 32) {
        int mye  = base + lane;
        int sidx = (mye < end) ? g_csr_src[mye] : 0;
        int cnt  = min(32, end - base);
        int j = 0;
        for (; j + 1 < cnt; j += 2) {
            int s0 = __shfl_sync(0xffffffffu, sidx, j);
            int s1 = __shfl_sync(0xffffffffu, sidx, j + 1);
            float4 v0 = *reinterpret_cast<const float4*>(h + (size_t)s0 * DD + lane * 4);
            float4 v1 = *reinterpret_cast<const float4*>(h + (size_t)s1 * DD + lane * 4);
            if (BN) {
                v0.x = fmaxf(fmaf(v0.x, sc.x, sh.x), 0.f);
                v0.y = fmaxf(fmaf(v0.y, sc.y, sh.y), 0.f);
                v0.z = fmaxf(fmaf(v0.z, sc.z, sh.z), 0.f);
                v0.w = fmaxf(fmaf(v0.w, sc.w, sh.w), 0.f);
                v1.x = fmaxf(fmaf(v1.x, sc.x, sh.x), 0.f);
                v1.y = fmaxf(fmaf(v1.y, sc.y, sh.y), 0.f);
                v1.z = fmaxf(fmaf(v1.z, sc.z, sh.z), 0.f);
                v1.w = fmaxf(fmaf(v1.w, sc.w, sh.w), 0.f);
            }
            acc.x += v0.x; acc.y += v0.y; acc.z += v0.z; acc.w += v0.w;
            acc.x += v1.x; acc.y += v1.y; acc.z += v1.z; acc.w += v1.w;
        }
        if (j < cnt) {
            int s0 = __shfl_sync(0xffffffffu, sidx, j);
            float4 v0 = *reinterpret_cast<const float4*>(h + (size_t)s0 * DD + lane * 4);
            if (BN) {
                v0.x = fmaxf(fmaf(v0.x, sc.x, sh.x), 0.f);
                v0.y = fmaxf(fmaf(v0.y, sc.y, sh.y), 0.f);
                v0.z = fmaxf(fmaf(v0.z, sc.z, sh.z), 0.f);
                v0.w = fmaxf(fmaf(v0.w, sc.w, sh.w), 0.f);
            }
            acc.x += v0.x; acc.y += v0.y; acc.z += v0.z; acc.w += v0.w;
        }
    }
    float rd = g_rdeg[node];
    acc.x *= rd; acc.y *= rd; acc.z *= rd; acc.w *= rd;
    *reinterpret_cast<float4*>(g_agg + (size_t)node * DD + lane * 4) = acc;
}

// ---------------- tf32 tensor-core dual GEMM + bias + residual --------------------
__device__ __forceinline__ uint32_t f2tf32(float x) {
    uint32_t r;
    asm("cvt.rna.tf32.f32 %0, %1;" : "=r"(r) : "f"(x));
    return r;
}

__device__ __forceinline__ void mma_tf32(float* d, const uint32_t* a, const uint32_t* b) {
    asm volatile(
        "mma.sync.aligned.m16n8k8.row.col.f32.tf32.tf32.f32 "
        "{%0,%1,%2,%3}, {%4,%5,%6,%7}, {%8,%9}, {%0,%1,%2,%3};\n"
        : "+f"(d[0]), "+f"(d[1]), "+f"(d[2]), "+f"(d[3])
        : "r"(a[0]), "r"(a[1]), "r"(a[2]), "r"(a[3]), "r"(b[0]), "r"(b[1]));
}

#define BM 128
#define BK 16
#define A_STRIDE 20
#define B_STRIDE 136

// BNIN: input h is raw pre-BN -> apply max(x*sc+sh,0) at every read of h.
template<bool BNIN>
__global__ __launch_bounds__(256, 2)
void k_gemm_tc(const float* __restrict__ h,
               const float* __restrict__ Ws, const float* __restrict__ Wn,
               const float* __restrict__ bias, float* __restrict__ out, int nrows) {
    __shared__ uint32_t Ah[128][A_STRIDE];
    __shared__ uint32_t Aa[128][A_STRIDE];
    __shared__ uint32_t Bs[BK][B_STRIDE];
    __shared__ uint32_t Bn[BK][B_STRIDE];

    const int tid  = threadIdx.x;
    const int warp = tid >> 5;
    const int lane = tid & 31;
    const int g    = lane >> 2;
    const int t    = lane & 3;
    const int wm   = warp & 3;
    const int wn   = warp >> 2;
    const int m0   = blockIdx.x * BM;
    const int wrow = wm * 32;
    const int wcol = wn * 64;

    float acc[2][8][4];
#pragma unroll
    for (int mt = 0; mt < 2; mt++)
#pragma unroll
        for (int nt = 0; nt < 8; nt++)
#pragma unroll
            for (int j = 0; j < 4; j++) acc[mt][nt][j] = 0.f;

    for (int kc = 0; kc < DD / BK; kc++) {
        const int ks = kc * BK;
#pragma unroll
        for (int r = 0; r < 2; r++) {
            int id  = tid + r * 256;
            int row = id >> 2;
            int c4  = id & 3;
            int grow = m0 + row;
            float4 vh = make_float4(0.f, 0.f, 0.f, 0.f);
            float4 va = make_float4(0.f, 0.f, 0.f, 0.f);
            if (grow < nrows) {
                size_t off = (size_t)grow * DD + ks + c4 * 4;
                vh = *reinterpret_cast<const float4*>(h + off);
                va = *reinterpret_cast<const float4*>(g_agg + off);
                if (BNIN) {
                    float4 s4 = *reinterpret_cast<const float4*>(g_sc + ks + c4 * 4);
                    float4 h4 = *reinterpret_cast<const float4*>(g_sh + ks + c4 * 4);
                    vh.x = fmaxf(fmaf(vh.x, s4.x, h4.x), 0.f);
                    vh.y = fmaxf(fmaf(vh.y, s4.y, h4.y), 0.f);
                    vh.z = fmaxf(fmaf(vh.z, s4.z, h4.z), 0.f);
                    vh.w = fmaxf(fmaf(vh.w, s4.w, h4.w), 0.f);
                }
            }
            uint4 ph = make_uint4(f2tf32(vh.x), f2tf32(vh.y), f2tf32(vh.z), f2tf32(vh.w));
            uint4 pa = make_uint4(f2tf32(va.x), f2tf32(va.y), f2tf32(va.z), f2tf32(va.w));
            *reinterpret_cast<uint4*>(&Ah[row][c4 * 4]) = ph;
            *reinterpret_cast<uint4*>(&Aa[row][c4 * 4]) = pa;
        }
#pragma unroll
        for (int r = 0; r < 2; r++) {
            int id  = tid + r * 256;
            int row = id >> 5;
            int c4  = id & 31;
            size_t off = (size_t)(ks + row) * DD + c4 * 4;
            float4 vs = *reinterpret_cast<const float4*>(Ws + off);
            float4 vn = *reinterpret_cast<const float4*>(Wn + off);
            uint4 ps = make_uint4(f2tf32(vs.x), f2tf32(vs.y), f2tf32(vs.z), f2tf32(vs.w));
            uint4 pn = make_uint4(f2tf32(vn.x), f2tf32(vn.y), f2tf32(vn.z), f2tf32(vn.w));
            *reinterpret_cast<uint4*>(&Bs[row][c4 * 4]) = ps;
            *reinterpret_cast<uint4*>(&Bn[row][c4 * 4]) = pn;
        }
        __syncthreads();

#pragma unroll
        for (int ks8 = 0; ks8 < BK / 8; ks8++) {
            const int kb = ks8 * 8;
            uint32_t a[2][4], b[8][2];
#pragma unroll
            for (int mt = 0; mt < 2; mt++) {
                int r = wrow + mt * 16;
                a[mt][0] = Ah[r + g][kb + t];
                a[mt][1] = Ah[r + g + 8][kb + t];
                a[mt][2] = Ah[r + g][kb + t + 4];
                a[mt][3] = Ah[r + g + 8][kb + t + 4];
            }
#pragma unroll
            for (int nt = 0; nt < 8; nt++) {
                int c = wcol + nt * 8 + g;
                b[nt][0] = Bs[kb + t][c];
                b[nt][1] = Bs[kb + t + 4][c];
            }
#pragma unroll
            for (int mt = 0; mt < 2; mt++)
#pragma unroll
                for (int nt = 0; nt < 8; nt++)
                    mma_tf32(acc[mt][nt], a[mt], b[nt]);
#pragma unroll
            for (int mt = 0; mt < 2; mt++) {
                int r = wrow + mt * 16;
                a[mt][0] = Aa[r + g][kb + t];
                a[mt][1] = Aa[r + g + 8][kb + t];
                a[mt][2] = Aa[r + g][kb + t + 4];
                a[mt][3] = Aa[r + g + 8][kb + t + 4];
            }
#pragma unroll
            for (int nt = 0; nt < 8; nt++) {
                int c = wcol + nt * 8 + g;
                b[nt][0] = Bn[kb + t][c];
                b[nt][1] = Bn[kb + t + 4][c];
            }
#pragma unroll
            for (int mt = 0; mt < 2; mt++)
#pragma unroll
                for (int nt = 0; nt < 8; nt++)
                    mma_tf32(acc[mt][nt], a[mt], b[nt]);
        }
        __syncthreads();
    }

    // epilogue: + bias + residual (BN(h) when BNIN), write raw out
#pragma unroll
    for (int mt = 0; mt < 2; mt++) {
#pragma unroll
        for (int rr = 0; rr < 2; rr++) {
            int grow = m0 + wrow + mt * 16 + g + rr * 8;
            if (grow < nrows) {
#pragma unroll
                for (int nt = 0; nt < 8; nt++) {
                    int col = wcol + nt * 8 + t * 2;
                    size_t off = (size_t)grow * DD + col;
                    float2 res = *reinterpret_cast<const float2*>(h + off);
                    if (BNIN) {
                        float2 s2 = *reinterpret_cast<const float2*>(g_sc + col);
                        float2 h2 = *reinterpret_cast<const float2*>(g_sh + col);
                        res.x = fmaxf(fmaf(res.x, s2.x, h2.x), 0.f);
                        res.y = fmaxf(fmaf(res.y, s2.y, h2.y), 0.f);
                    }
                    float2 bv = *reinterpret_cast<const float2*>(bias + col);
                    float2 o;
                    o.x = acc[mt][nt][rr * 2 + 0] + bv.x + res.x;
                    o.y = acc[mt][nt][rr * 2 + 1] + bv.y + res.y;
                    *reinterpret_cast<float2*>(out + off) = o;
                }
            }
        }
    }
}

// ---------------- column stats (sum, sumsq) over raw pre-BN output ----------------
__global__ __launch_bounds__(256)
void k_stats(const float* __restrict__ x, int n) {
    __shared__ float sh[8][DD];
    __shared__ float shq[8][DD];
    int lane = threadIdx.x & 31;
    int w    = threadIdx.x >> 5;
    int c    = lane * 4;
    float4 s = make_float4(0.f, 0.f, 0.f, 0.f);
    float4 q = make_float4(0.f, 0.f, 0.f, 0.f);
    for (int r = blockIdx.x * 8 + w; r < n; r += gridDim.x * 8) {
        float4 v = *reinterpret_cast<const float4*>(x + (size_t)r * DD + c);
        s.x += v.x; s.y += v.y; s.z += v.z; s.w += v.w;
        q.x += v.x * v.x; q.y += v.y * v.y; q.z += v.z * v.z; q.w += v.w * v.w;
    }
    *reinterpret_cast<float4*>(&sh[w][c])  = s;
    *reinterpret_cast<float4*>(&shq[w][c]) = q;
    __syncthreads();
    if (threadIdx.x < DD) {
        float ss = 0.f, qq = 0.f;
#pragma unroll
        for (int r = 0; r < 8; r++) { ss += sh[r][threadIdx.x]; qq += shq[r][threadIdx.x]; }
        atomicAdd(&g_stats[threadIdx.x], ss);
        atomicAdd(&g_stats[DD + threadIdx.x], qq);
    }
}

// ---------------- finalize: stats -> (sc, sh), reset stats ----------------
__global__ void k_finalize(const float* __restrict__ gamma, const float* __restrict__ beta,
                           float n) {
    int i = threadIdx.x;
    if (i < DD) {
        float inv = 1.0f / n;
        float mu  = g_stats[i] * inv;
        float var = g_stats[DD + i] * inv - mu * mu;
        float scv = rsqrtf(var + EPS) * gamma[i];
        g_sc[i] = scv;
        g_sh[i] = beta[i] - mu * scv;
        g_stats[i] = 0.f;
        g_stats[DD + i] = 0.f;
    }
}

// ---------------- launch ----------------
extern "C" void kernel_launch(void* const* d_in, const int* in_sizes, int n_in,
                              void* d_out, int out_size) {
    const float* feat   = (const float*)d_in[0];
    const int*   src    = (const int*)d_in[1];
    const int*   dst    = (const int*)d_in[2];
    const float* Wself  = (const float*)d_in[3];
    const float* Wneigh = (const float*)d_in[4];
    const float* bias   = (const float*)d_in[5];
    const float* gamma  = (const float*)d_in[6];
    const float* beta   = (const float*)d_in[7];
    float* out = (float*)d_out;

    const int N = in_sizes[0] / DD;
    const int E = in_sizes[1];

    void *p_deg, *p_stats, *p_h1, *p_h2;
    cudaGetSymbolAddress(&p_deg, g_deg);
    cudaGetSymbolAddress(&p_stats, g_stats);
    cudaGetSymbolAddress(&p_h1, g_h1);
    cudaGetSymbolAddress(&p_h2, g_h2);

    // ---- CSR build ----
    const int nb = (N + 255) / 256;
    cudaMemsetAsync(p_deg, 0, (size_t)N * sizeof(int), 0);
    cudaMemsetAsync(p_stats, 0, 2 * DD * sizeof(float), 0);
    k_count_deg<<<(E + 255) / 256, 256>>>(dst, E);
    k_scan1<<<nb, 256>>>(N);
    k_scan2<<<1, 256>>>(nb);
    k_scan3<<<nb, 256>>>(N, E);
    k_fill<<<(E + 255) / 256, 256>>>(src, dst, E);

    const int gemm_blocks   = (N + BM - 1) / BM;
    const int gather_blocks = (N + 7) / 8;       // warp per node, 8 warps/block

    const float* raw_in[3]  = {feat, (const float*)p_h1, (const float*)p_h2};
    float*       raw_out[3] = {(float*)p_h1, (float*)p_h2, out};

    for (int l = 0; l < 3; l++) {
        const float* Ws = Wself + (size_t)l * DD * DD;
        const float* Wn = Wneigh + (size_t)l * DD * DD;
        const float* bl = bias + (size_t)l * DD;
        const float* hin = raw_in[l];
        float* ho = raw_out[l];

        if (l == 0) k_gather<false><<<gather_blocks, 256>>>(hin, N);
        else        k_gather<true ><<<gather_blocks, 256>>>(hin, N);

        if (l == 0) k_gemm_tc<false><<<gemm_blocks, 256>>>(hin, Ws, Wn, bl, ho, N);
        else        k_gemm_tc<true ><<<gemm_blocks, 256>>>(hin, Ws, Wn, bl, ho, N);

        if (l < 2) {
            k_stats<<<128, 256>>>((const float*)ho, N);
            k_finalize<<<1, 128>>>(gamma + (size_t)l * DD, beta + (size_t)l * DD, (float)N);
        }
    }
    (void)n_in; (void)out_size;
}

// round 13
// speedup vs baseline: 1.7111x; 1.0569x over previous
#include <cuda_runtime.h>
#include <cuda_fp16.h>
#include <stdint.h>

#define NODES 50000
#define EDGES 800000
#define DD    128
#define EPS   1e-5f

// ---------------- scratch (static device globals; no allocation) ----------------
__device__ float  g_agg[(size_t)NODES * DD];
__device__ float  g_h1[(size_t)NODES * DD];   // pre-BN layer output
__device__ float  g_h2[(size_t)NODES * DD];   // post-BN layer output
__device__ __half g_hh[(size_t)NODES * DD];   // fp16 shadow of current h (gather input)
__device__ float  g_rdeg[NODES];
__device__ int    g_deg[NODES];
__device__ int    g_csr_ptr[NODES + 1];
__device__ int    g_cursor[NODES];
__device__ int    g_csr_src[EDGES];
__device__ int    g_bsum[256];
__device__ int    g_boff[256];
__device__ float  g_stats[2 * DD];            // [0:128) col sums, [128:256) sumsq

// ---------------- degree + CSR build ----------------
__global__ void k_count_deg(const int* __restrict__ dst, int e) {
    int i = blockIdx.x * blockDim.x + threadIdx.x;
    if (i < e) atomicAdd(&g_deg[dst[i]], 1);
}

__global__ void k_scan1(int n) {
    __shared__ int s[256];
    int tid = threadIdx.x;
    int i = blockIdx.x * 256 + tid;
    int v = (i < n) ? g_deg[i] : 0;
    s[tid] = v;
    __syncthreads();
#pragma unroll
    for (int o = 1; o < 256; o <<= 1) {
        int x = (tid >= o) ? s[tid - o] : 0;
        __syncthreads();
        s[tid] += x;
        __syncthreads();
    }
    if (i < n) g_csr_ptr[i] = s[tid] - v;
    if (tid == 255) g_bsum[blockIdx.x] = s[255];
}

__global__ void k_scan2(int nb) {
    __shared__ int s[256];
    int tid = threadIdx.x;
    int v = (tid < nb) ? g_bsum[tid] : 0;
    s[tid] = v;
    __syncthreads();
#pragma unroll
    for (int o = 1; o < 256; o <<= 1) {
        int x = (tid >= o) ? s[tid - o] : 0;
        __syncthreads();
        s[tid] += x;
        __syncthreads();
    }
    if (tid < nb) g_boff[tid] = s[tid] - v;
}

__global__ void k_scan3(int n, int e) {
    int i = blockIdx.x * blockDim.x + threadIdx.x;
    if (i < n) {
        int p = g_csr_ptr[i] + g_boff[blockIdx.x];
        g_csr_ptr[i] = p;
        g_cursor[i] = p;
        int d = g_deg[i];
        g_rdeg[i] = 1.0f / (float)(d > 0 ? d : 1);
    }
    if (i == 0) g_csr_ptr[n] = e;
}

__global__ void k_fill(const int* __restrict__ src, const int* __restrict__ dst, int e) {
    int i = blockIdx.x * blockDim.x + threadIdx.x;
    if (i < e) {
        int pos = atomicAdd(&g_cursor[dst[i]], 1);
        g_csr_src[pos] = src[i];
    }
}

// ---------------- fp16 shadow of feat ----------------
__global__ void k_tohalf(const float* __restrict__ x, int total4) {
    int idx = blockIdx.x * blockDim.x + threadIdx.x;   // one float4 -> 4 halves
    if (idx >= total4) return;
    float4 v = reinterpret_cast<const float4*>(x)[idx];
    __half2 lo = __floats2half2_rn(v.x, v.y);
    __half2 hi = __floats2half2_rn(v.z, v.w);
    uint2 u;
    u.x = *reinterpret_cast<uint32_t*>(&lo);
    u.y = *reinterpret_cast<uint32_t*>(&hi);
    reinterpret_cast<uint2*>(g_hh)[idx] = u;
}

// ---------------- gather: one warp per dst node, fp16 rows, mean ----------------
__global__ __launch_bounds__(256)
void k_gather(int n) {
    int node = (blockIdx.x * blockDim.x + threadIdx.x) >> 5;
    int lane = threadIdx.x & 31;
    if (node >= n) return;
    const __half* hh = g_hh;
    int beg = g_csr_ptr[node];
    int end = g_csr_ptr[node + 1];
    float4 acc = make_float4(0.f, 0.f, 0.f, 0.f);
    for (int base = beg; base < end; base += 32) {
        int mye  = base + lane;
        int sidx = (mye < end) ? g_csr_src[mye] : 0;
        int cnt  = min(32, end - base);
        int j = 0;
        for (; j + 3 < cnt; j += 4) {
            int s0 = __shfl_sync(0xffffffffu, sidx, j);
            int s1 = __shfl_sync(0xffffffffu, sidx, j + 1);
            int s2 = __shfl_sync(0xffffffffu, sidx, j + 2);
            int s3 = __shfl_sync(0xffffffffu, sidx, j + 3);
            uint2 u0 = *reinterpret_cast<const uint2*>(hh + (size_t)s0 * DD + lane * 4);
            uint2 u1 = *reinterpret_cast<const uint2*>(hh + (size_t)s1 * DD + lane * 4);
            uint2 u2 = *reinterpret_cast<const uint2*>(hh + (size_t)s2 * DD + lane * 4);
            uint2 u3 = *reinterpret_cast<const uint2*>(hh + (size_t)s3 * DD + lane * 4);
            float2 a0 = __half22float2(*reinterpret_cast<__half2*>(&u0.x));
            float2 b0 = __half22float2(*reinterpret_cast<__half2*>(&u0.y));
            float2 a1 = __half22float2(*reinterpret_cast<__half2*>(&u1.x));
            float2 b1 = __half22float2(*reinterpret_cast<__half2*>(&u1.y));
            float2 a2 = __half22float2(*reinterpret_cast<__half2*>(&u2.x));
            float2 b2 = __half22float2(*reinterpret_cast<__half2*>(&u2.y));
            float2 a3 = __half22float2(*reinterpret_cast<__half2*>(&u3.x));
            float2 b3 = __half22float2(*reinterpret_cast<__half2*>(&u3.y));
            acc.x += a0.x + a1.x + a2.x + a3.x;
            acc.y += a0.y + a1.y + a2.y + a3.y;
            acc.z += b0.x + b1.x + b2.x + b3.x;
            acc.w += b0.y + b1.y + b2.y + b3.y;
        }
        for (; j < cnt; j++) {
            int s0 = __shfl_sync(0xffffffffu, sidx, j);
            uint2 u0 = *reinterpret_cast<const uint2*>(hh + (size_t)s0 * DD + lane * 4);
            float2 a0 = __half22float2(*reinterpret_cast<__half2*>(&u0.x));
            float2 b0 = __half22float2(*reinterpret_cast<__half2*>(&u0.y));
            acc.x += a0.x; acc.y += a0.y; acc.z += b0.x; acc.w += b0.y;
        }
    }
    float rd = g_rdeg[node];
    acc.x *= rd; acc.y *= rd; acc.z *= rd; acc.w *= rd;
    *reinterpret_cast<float4*>(g_agg + (size_t)node * DD + lane * 4) = acc;
}

// ---------------- tf32 tensor-core dual GEMM + bias + residual ----------------
__device__ __forceinline__ uint32_t f2tf32(float x) {
    uint32_t r;
    asm("cvt.rna.tf32.f32 %0, %1;" : "=r"(r) : "f"(x));
    return r;
}

__device__ __forceinline__ void mma_tf32(float* d, const uint32_t* a, const uint32_t* b) {
    asm volatile(
        "mma.sync.aligned.m16n8k8.row.col.f32.tf32.tf32.f32 "
        "{%0,%1,%2,%3}, {%4,%5,%6,%7}, {%8,%9}, {%0,%1,%2,%3};\n"
        : "+f"(d[0]), "+f"(d[1]), "+f"(d[2]), "+f"(d[3])
        : "r"(a[0]), "r"(a[1]), "r"(a[2]), "r"(a[3]), "r"(b[0]), "r"(b[1]));
}

#define BM 128
#define BK 16
#define A_STRIDE 20
#define B_STRIDE 136

__global__ __launch_bounds__(256, 2)
void k_gemm_tc(const float* __restrict__ h,
               const float* __restrict__ Ws, const float* __restrict__ Wn,
               const float* __restrict__ bias, float* __restrict__ out, int nrows) {
    __shared__ uint32_t Ah[128][A_STRIDE];
    __shared__ uint32_t Aa[128][A_STRIDE];
    __shared__ uint32_t Bs[BK][B_STRIDE];
    __shared__ uint32_t Bn[BK][B_STRIDE];

    const int tid  = threadIdx.x;
    const int warp = tid >> 5;
    const int lane = tid & 31;
    const int g    = lane >> 2;
    const int t    = lane & 3;
    const int wm   = warp & 3;
    const int wn   = warp >> 2;
    const int m0   = blockIdx.x * BM;
    const int wrow = wm * 32;
    const int wcol = wn * 64;

    float acc[2][8][4];
#pragma unroll
    for (int mt = 0; mt < 2; mt++)
#pragma unroll
        for (int nt = 0; nt < 8; nt++)
#pragma unroll
            for (int j = 0; j < 4; j++) acc[mt][nt][j] = 0.f;

    for (int kc = 0; kc < DD / BK; kc++) {
        const int ks = kc * BK;
#pragma unroll
        for (int r = 0; r < 2; r++) {
            int id  = tid + r * 256;
            int row = id >> 2;
            int c4  = id & 3;
            int grow = m0 + row;
            float4 vh = make_float4(0.f, 0.f, 0.f, 0.f);
            float4 va = make_float4(0.f, 0.f, 0.f, 0.f);
            if (grow < nrows) {
                size_t off = (size_t)grow * DD + ks + c4 * 4;
                vh = *reinterpret_cast<const float4*>(h + off);
                va = *reinterpret_cast<const float4*>(g_agg + off);
            }
            uint4 ph = make_uint4(f2tf32(vh.x), f2tf32(vh.y), f2tf32(vh.z), f2tf32(vh.w));
            uint4 pa = make_uint4(f2tf32(va.x), f2tf32(va.y), f2tf32(va.z), f2tf32(va.w));
            *reinterpret_cast<uint4*>(&Ah[row][c4 * 4]) = ph;
            *reinterpret_cast<uint4*>(&Aa[row][c4 * 4]) = pa;
        }
#pragma unroll
        for (int r = 0; r < 2; r++) {
            int id  = tid + r * 256;
            int row = id >> 5;
            int c4  = id & 31;
            size_t off = (size_t)(ks + row) * DD + c4 * 4;
            float4 vs = *reinterpret_cast<const float4*>(Ws + off);
            float4 vn = *reinterpret_cast<const float4*>(Wn + off);
            uint4 ps = make_uint4(f2tf32(vs.x), f2tf32(vs.y), f2tf32(vs.z), f2tf32(vs.w));
            uint4 pn = make_uint4(f2tf32(vn.x), f2tf32(vn.y), f2tf32(vn.z), f2tf32(vn.w));
            *reinterpret_cast<uint4*>(&Bs[row][c4 * 4]) = ps;
            *reinterpret_cast<uint4*>(&Bn[row][c4 * 4]) = pn;
        }
        __syncthreads();

#pragma unroll
        for (int ks8 = 0; ks8 < BK / 8; ks8++) {
            const int kb = ks8 * 8;
            uint32_t a[2][4], b[8][2];
#pragma unroll
            for (int mt = 0; mt < 2; mt++) {
                int r = wrow + mt * 16;
                a[mt][0] = Ah[r + g][kb + t];
                a[mt][1] = Ah[r + g + 8][kb + t];
                a[mt][2] = Ah[r + g][kb + t + 4];
                a[mt][3] = Ah[r + g + 8][kb + t + 4];
            }
#pragma unroll
            for (int nt = 0; nt < 8; nt++) {
                int c = wcol + nt * 8 + g;
                b[nt][0] = Bs[kb + t][c];
                b[nt][1] = Bs[kb + t + 4][c];
            }
#pragma unroll
            for (int mt = 0; mt < 2; mt++)
#pragma unroll
                for (int nt = 0; nt < 8; nt++)
                    mma_tf32(acc[mt][nt], a[mt], b[nt]);
#pragma unroll
            for (int mt = 0; mt < 2; mt++) {
                int r = wrow + mt * 16;
                a[mt][0] = Aa[r + g][kb + t];
                a[mt][1] = Aa[r + g + 8][kb + t];
                a[mt][2] = Aa[r + g][kb + t + 4];
                a[mt][3] = Aa[r + g + 8][kb + t + 4];
            }
#pragma unroll
            for (int nt = 0; nt < 8; nt++) {
                int c = wcol + nt * 8 + g;
                b[nt][0] = Bn[kb + t][c];
                b[nt][1] = Bn[kb + t + 4][c];
            }
#pragma unroll
            for (int mt = 0; mt < 2; mt++)
#pragma unroll
                for (int nt = 0; nt < 8; nt++)
                    mma_tf32(acc[mt][nt], a[mt], b[nt]);
        }
        __syncthreads();
    }

#pragma unroll
    for (int mt = 0; mt < 2; mt++) {
#pragma unroll
        for (int rr = 0; rr < 2; rr++) {
            int grow = m0 + wrow + mt * 16 + g + rr * 8;
            if (grow < nrows) {
#pragma unroll
                for (int nt = 0; nt < 8; nt++) {
                    int col = wcol + nt * 8 + t * 2;
                    size_t off = (size_t)grow * DD + col;
                    float2 res = *reinterpret_cast<const float2*>(h + off);
                    float2 bv  = *reinterpret_cast<const float2*>(bias + col);
                    float2 o;
                    o.x = acc[mt][nt][rr * 2 + 0] + bv.x + res.x;
                    o.y = acc[mt][nt][rr * 2 + 1] + bv.y + res.y;
                    *reinterpret_cast<float2*>(out + off) = o;
                }
            }
        }
    }
}

// ---------------- column stats (sum, sumsq) ----------------
__global__ __launch_bounds__(256)
void k_stats(const float* __restrict__ x, int n) {
    __shared__ float sh[8][DD];
    __shared__ float shq[8][DD];
    int lane = threadIdx.x & 31;
    int w    = threadIdx.x >> 5;
    int c    = lane * 4;
    float4 s = make_float4(0.f, 0.f, 0.f, 0.f);
    float4 q = make_float4(0.f, 0.f, 0.f, 0.f);
    for (int r = blockIdx.x * 8 + w; r < n; r += gridDim.x * 8) {
        float4 v = *reinterpret_cast<const float4*>(x + (size_t)r * DD + c);
        s.x += v.x; s.y += v.y; s.z += v.z; s.w += v.w;
        q.x += v.x * v.x; q.y += v.y * v.y; q.z += v.z * v.z; q.w += v.w * v.w;
    }
    *reinterpret_cast<float4*>(&sh[w][c])  = s;
    *reinterpret_cast<float4*>(&shq[w][c]) = q;
    __syncthreads();
    if (threadIdx.x < DD) {
        float ss = 0.f, qq = 0.f;
#pragma unroll
        for (int r = 0; r < 8; r++) { ss += sh[r][threadIdx.x]; qq += shq[r][threadIdx.x]; }
        atomicAdd(&g_stats[threadIdx.x], ss);
        atomicAdd(&g_stats[DD + threadIdx.x], qq);
    }
}

// ---------------- BN (train-mode, biased var) + ReLU; also emits fp16 shadow -------
__global__ void k_bn_relu(const float* __restrict__ hn, const float* __restrict__ gamma,
                          const float* __restrict__ beta, float* __restrict__ out, int n) {
    int idx   = blockIdx.x * blockDim.x + threadIdx.x;
    int total = n * (DD / 4);
    if (idx >= total) return;
    int c4 = idx & 31;
    int c  = c4 * 4;
    float inv = 1.0f / (float)n;

    float4 v = reinterpret_cast<const float4*>(hn)[idx];
    float4 o;
#define BN_ONE(comp, cc)                                            \
    {                                                               \
        float mu  = g_stats[cc] * inv;                              \
        float var = g_stats[DD + cc] * inv - mu * mu;               \
        float sc  = rsqrtf(var + EPS) * __ldg(gamma + cc);          \
        float sh  = __ldg(beta + cc) - mu * sc;                     \
        o.comp = fmaxf(fmaf(v.comp, sc, sh), 0.f);                  \
    }
    BN_ONE(x, c + 0)
    BN_ONE(y, c + 1)
    BN_ONE(z, c + 2)
    BN_ONE(w, c + 3)
#undef BN_ONE
    reinterpret_cast<float4*>(out)[idx] = o;
    __half2 lo = __floats2half2_rn(o.x, o.y);
    __half2 hi = __floats2half2_rn(o.z, o.w);
    uint2 u;
    u.x = *reinterpret_cast<uint32_t*>(&lo);
    u.y = *reinterpret_cast<uint32_t*>(&hi);
    reinterpret_cast<uint2*>(g_hh)[idx] = u;
}

// ---------------- launch ----------------
extern "C" void kernel_launch(void* const* d_in, const int* in_sizes, int n_in,
                              void* d_out, int out_size) {
    const float* feat   = (const float*)d_in[0];
    const int*   src    = (const int*)d_in[1];
    const int*   dst    = (const int*)d_in[2];
    const float* Wself  = (const float*)d_in[3];
    const float* Wneigh = (const float*)d_in[4];
    const float* bias   = (const float*)d_in[5];
    const float* gamma  = (const float*)d_in[6];
    const float* beta   = (const float*)d_in[7];
    float* out = (float*)d_out;

    const int N = in_sizes[0] / DD;
    const int E = in_sizes[1];

    void *p_deg, *p_stats, *p_h1, *p_h2;
    cudaGetSymbolAddress(&p_deg, g_deg);
    cudaGetSymbolAddress(&p_stats, g_stats);
    cudaGetSymbolAddress(&p_h1, g_h1);
    cudaGetSymbolAddress(&p_h2, g_h2);

    // ---- CSR build + fp16 shadow of feat ----
    const int nb = (N + 255) / 256;
    cudaMemsetAsync(p_deg, 0, (size_t)N * sizeof(int), 0);
    k_tohalf<<<(N * (DD / 4) + 255) / 256, 256>>>(feat, N * (DD / 4));
    k_count_deg<<<(E + 255) / 256, 256>>>(dst, E);
    k_scan1<<<nb, 256>>>(N);
    k_scan2<<<1, 256>>>(nb);
    k_scan3<<<nb, 256>>>(N, E);
    k_fill<<<(E + 255) / 256, 256>>>(src, dst, E);

    const int gemm_blocks   = (N + BM - 1) / BM;
    const int gather_blocks = (N + 7) / 8;       // warp per node, 8 warps/block
    const int bn_blocks     = (N * (DD / 4) + 255) / 256;

    const float* hcur = feat;
    for (int l = 0; l < 3; l++) {
        k_gather<<<gather_blocks, 256>>>(N);

        const float* Ws = Wself + (size_t)l * DD * DD;
        const float* Wn = Wneigh + (size_t)l * DD * DD;
        const float* bl = bias + (size_t)l * DD;

        if (l < 2) {
            cudaMemsetAsync(p_stats, 0, 2 * DD * sizeof(float), 0);
            k_gemm_tc<<<gemm_blocks, 256>>>(hcur, Ws, Wn, bl, (float*)p_h1, N);
            k_stats<<<128, 256>>>((const float*)p_h1, N);
            k_bn_relu<<<bn_blocks, 256>>>((const float*)p_h1,
                                          gamma + (size_t)l * DD,
                                          beta + (size_t)l * DD,
                                          (float*)p_h2, N);
            hcur = (const float*)p_h2;
        } else {
            k_gemm_tc<<<gemm_blocks, 256>>>(hcur, Ws, Wn, bl, out, N);
        }
    }
    (void)n_in; (void)out_size;
}

// round 14
// speedup vs baseline: 1.7864x; 1.0440x over previous
#include <cuda_runtime.h>
#include <cuda_fp16.h>
#include <stdint.h>

#define NODES 50000
#define EDGES 800000
#define DD    128
#define EPS   1e-5f

// ---------------- scratch (static device globals; no allocation) ----------------
__device__ __half g_aggh[(size_t)NODES * DD]; // fp16 agg (gather output, GEMM input)
__device__ float  g_h1[(size_t)NODES * DD];   // pre-BN layer output
__device__ float  g_h2[(size_t)NODES * DD];   // post-BN layer output
__device__ __half g_hh[(size_t)NODES * DD];   // fp16 shadow of current h
__device__ __half g_wh[6 * DD * DD];          // fp16 weights: [l]=self, [3+l]=neigh
__device__ float  g_rdeg[NODES];
__device__ int    g_deg[NODES];
__device__ int    g_csr_ptr[NODES + 1];
__device__ int    g_cursor[NODES];
__device__ int    g_csr_src[EDGES];
__device__ int    g_bsum[256];
__device__ float  g_stats[2 * DD];

// ---------------- degree + CSR build ----------------
__global__ void k_count_deg(const int* __restrict__ dst, int e) {
    int i = blockIdx.x * blockDim.x + threadIdx.x;
    if (i < e) atomicAdd(&g_deg[dst[i]], 1);
}

__global__ void k_scan1(int n) {
    __shared__ int s[256];
    int tid = threadIdx.x;
    int i = blockIdx.x * 256 + tid;
    int v = (i < n) ? g_deg[i] : 0;
    s[tid] = v;
    __syncthreads();
#pragma unroll
    for (int o = 1; o < 256; o <<= 1) {
        int x = (tid >= o) ? s[tid - o] : 0;
        __syncthreads();
        s[tid] += x;
        __syncthreads();
    }
    if (i < n) g_csr_ptr[i] = s[tid] - v;   // block-local exclusive
    if (tid == 255) g_bsum[blockIdx.x] = s[255];
}

// scan3 with inline block-offset reduction (replaces old scan2+scan3)
__global__ void k_scan3(int n, int e) {
    __shared__ int s[256];
    int tid = threadIdx.x;
    int partial = 0;
    for (int j = tid; j < blockIdx.x; j += 256) partial += g_bsum[j];
    s[tid] = partial;
    __syncthreads();
#pragma unroll
    for (int o = 128; o > 0; o >>= 1) {
        if (tid < o) s[tid] += s[tid + o];
        __syncthreads();
    }
    int boff = s[0];
    int i = blockIdx.x * 256 + tid;
    if (i < n) {
        int p = g_csr_ptr[i] + boff;
        g_csr_ptr[i] = p;
        g_cursor[i] = p;
        int d = g_deg[i];
        g_rdeg[i] = 1.0f / (float)(d > 0 ? d : 1);
    }
    if (i == 0) g_csr_ptr[n] = e;
}

__global__ void k_fill(const int* __restrict__ src, const int* __restrict__ dst, int e) {
    int i = blockIdx.x * blockDim.x + threadIdx.x;
    if (i < e) {
        int pos = atomicAdd(&g_cursor[dst[i]], 1);
        g_csr_src[pos] = src[i];
    }
}

// ---------------- fp16 shadows: feat + both weight tensors (one launch) -----------
__global__ void k_tohalf_all(const float* __restrict__ feat,
                             const float* __restrict__ Wself,
                             const float* __restrict__ Wneigh,
                             int feat4, int w4) {   // counts in float4 units
    int idx = blockIdx.x * blockDim.x + threadIdx.x;
    if (idx < feat4) {
        float4 v = reinterpret_cast<const float4*>(feat)[idx];
        __half2 lo = __floats2half2_rn(v.x, v.y);
        __half2 hi = __floats2half2_rn(v.z, v.w);
        uint2 u;
        u.x = *reinterpret_cast<uint32_t*>(&lo);
        u.y = *reinterpret_cast<uint32_t*>(&hi);
        reinterpret_cast<uint2*>(g_hh)[idx] = u;
    } else if (idx < feat4 + 2 * w4) {
        int k = idx - feat4;
        const float* srcp = (k < w4) ? Wself : Wneigh;
        int j = (k < w4) ? k : k - w4;               // float4 index within tensor
        __half* dstp = g_wh + ((k < w4) ? 0 : 3 * DD * DD);
        float4 v = reinterpret_cast<const float4*>(srcp)[j];
        __half2 lo = __floats2half2_rn(v.x, v.y);
        __half2 hi = __floats2half2_rn(v.z, v.w);
        uint2 u;
        u.x = *reinterpret_cast<uint32_t*>(&lo);
        u.y = *reinterpret_cast<uint32_t*>(&hi);
        reinterpret_cast<uint2*>(dstp)[j] = u;
    }
}

// ---------------- gather: one warp per dst node, fp16 rows, fp16 agg out ----------
__global__ __launch_bounds__(256)
void k_gather(int n) {
    int node = (blockIdx.x * blockDim.x + threadIdx.x) >> 5;
    int lane = threadIdx.x & 31;
    if (node >= n) return;
    const __half* hh = g_hh;
    int beg = g_csr_ptr[node];
    int end = g_csr_ptr[node + 1];
    float4 acc = make_float4(0.f, 0.f, 0.f, 0.f);
    for (int base = beg; base < end; base += 32) {
        int mye  = base + lane;
        int sidx = (mye < end) ? g_csr_src[mye] : 0;
        int cnt  = min(32, end - base);
        int j = 0;
        for (; j + 3 < cnt; j += 4) {
            int s0 = __shfl_sync(0xffffffffu, sidx, j);
            int s1 = __shfl_sync(0xffffffffu, sidx, j + 1);
            int s2 = __shfl_sync(0xffffffffu, sidx, j + 2);
            int s3 = __shfl_sync(0xffffffffu, sidx, j + 3);
            uint2 u0 = *reinterpret_cast<const uint2*>(hh + (size_t)s0 * DD + lane * 4);
            uint2 u1 = *reinterpret_cast<const uint2*>(hh + (size_t)s1 * DD + lane * 4);
            uint2 u2 = *reinterpret_cast<const uint2*>(hh + (size_t)s2 * DD + lane * 4);
            uint2 u3 = *reinterpret_cast<const uint2*>(hh + (size_t)s3 * DD + lane * 4);
            float2 a0 = __half22float2(*reinterpret_cast<__half2*>(&u0.x));
            float2 b0 = __half22float2(*reinterpret_cast<__half2*>(&u0.y));
            float2 a1 = __half22float2(*reinterpret_cast<__half2*>(&u1.x));
            float2 b1 = __half22float2(*reinterpret_cast<__half2*>(&u1.y));
            float2 a2 = __half22float2(*reinterpret_cast<__half2*>(&u2.x));
            float2 b2 = __half22float2(*reinterpret_cast<__half2*>(&u2.y));
            float2 a3 = __half22float2(*reinterpret_cast<__half2*>(&u3.x));
            float2 b3 = __half22float2(*reinterpret_cast<__half2*>(&u3.y));
            acc.x += a0.x + a1.x + a2.x + a3.x;
            acc.y += a0.y + a1.y + a2.y + a3.y;
            acc.z += b0.x + b1.x + b2.x + b3.x;
            acc.w += b0.y + b1.y + b2.y + b3.y;
        }
        for (; j < cnt; j++) {
            int s0 = __shfl_sync(0xffffffffu, sidx, j);
            uint2 u0 = *reinterpret_cast<const uint2*>(hh + (size_t)s0 * DD + lane * 4);
            float2 a0 = __half22float2(*reinterpret_cast<__half2*>(&u0.x));
            float2 b0 = __half22float2(*reinterpret_cast<__half2*>(&u0.y));
            acc.x += a0.x; acc.y += a0.y; acc.z += b0.x; acc.w += b0.y;
        }
    }
    float rd = g_rdeg[node];
    __half2 lo = __floats2half2_rn(acc.x * rd, acc.y * rd);
    __half2 hi = __floats2half2_rn(acc.z * rd, acc.w * rd);
    uint2 u;
    u.x = *reinterpret_cast<uint32_t*>(&lo);
    u.y = *reinterpret_cast<uint32_t*>(&hi);
    *reinterpret_cast<uint2*>(g_aggh + (size_t)node * DD + lane * 4) = u;
}

// ---------------- tf32 tensor-core dual GEMM + bias + residual ----------------
__device__ __forceinline__ uint32_t f2tf32(float x) {
    uint32_t r;
    asm("cvt.rna.tf32.f32 %0, %1;" : "=r"(r) : "f"(x));
    return r;
}

__device__ __forceinline__ void mma_tf32(float* d, const uint32_t* a, const uint32_t* b) {
    asm volatile(
        "mma.sync.aligned.m16n8k8.row.col.f32.tf32.tf32.f32 "
        "{%0,%1,%2,%3}, {%4,%5,%6,%7}, {%8,%9}, {%0,%1,%2,%3};\n"
        : "+f"(d[0]), "+f"(d[1]), "+f"(d[2]), "+f"(d[3])
        : "r"(a[0]), "r"(a[1]), "r"(a[2]), "r"(a[3]), "r"(b[0]), "r"(b[1]));
}

__device__ __forceinline__ uint4 h4_to_tf32(uint2 u) {
    float2 a = __half22float2(*reinterpret_cast<__half2*>(&u.x));
    float2 b = __half22float2(*reinterpret_cast<__half2*>(&u.y));
    return make_uint4(f2tf32(a.x), f2tf32(a.y), f2tf32(b.x), f2tf32(b.y));
}

#define BM 128
#define BK 16
#define A_STRIDE 20
#define B_STRIDE 136

// A-tiles read from fp16 shadow + fp16 agg; B from fp16 weights; residual f32.
__global__ __launch_bounds__(256, 2)
void k_gemm_tc(const float* __restrict__ h,
               const __half* __restrict__ Wsh, const __half* __restrict__ Wnh,
               const float* __restrict__ bias, float* __restrict__ out, int nrows) {
    __shared__ uint32_t Ah[128][A_STRIDE];
    __shared__ uint32_t Aa[128][A_STRIDE];
    __shared__ uint32_t Bs[BK][B_STRIDE];
    __shared__ uint32_t Bn[BK][B_STRIDE];

    const int tid  = threadIdx.x;
    const int warp = tid >> 5;
    const int lane = tid & 31;
    const int g    = lane >> 2;
    const int t    = lane & 3;
    const int wm   = warp & 3;
    const int wn   = warp >> 2;
    const int m0   = blockIdx.x * BM;
    const int wrow = wm * 32;
    const int wcol = wn * 64;

    float acc[2][8][4];
#pragma unroll
    for (int mt = 0; mt < 2; mt++)
#pragma unroll
        for (int nt = 0; nt < 8; nt++)
#pragma unroll
            for (int j = 0; j < 4; j++) acc[mt][nt][j] = 0.f;

    for (int kc = 0; kc < DD / BK; kc++) {
        const int ks = kc * BK;
#pragma unroll
        for (int r = 0; r < 2; r++) {
            int id  = tid + r * 256;
            int row = id >> 2;
            int c4  = id & 3;
            int grow = m0 + row;
            uint2 uh = make_uint2(0u, 0u);
            uint2 ua = make_uint2(0u, 0u);
            if (grow < nrows) {
                size_t off = (size_t)grow * DD + ks + c4 * 4;
                uh = *reinterpret_cast<const uint2*>(g_hh + off);
                ua = *reinterpret_cast<const uint2*>(g_aggh + off);
            }
            *reinterpret_cast<uint4*>(&Ah[row][c4 * 4]) = h4_to_tf32(uh);
            *reinterpret_cast<uint4*>(&Aa[row][c4 * 4]) = h4_to_tf32(ua);
        }
#pragma unroll
        for (int r = 0; r < 2; r++) {
            int id  = tid + r * 256;
            int row = id >> 5;
            int c4  = id & 31;
            size_t off = (size_t)(ks + row) * DD + c4 * 4;
            uint2 us = *reinterpret_cast<const uint2*>(Wsh + off);
            uint2 un = *reinterpret_cast<const uint2*>(Wnh + off);
            *reinterpret_cast<uint4*>(&Bs[row][c4 * 4]) = h4_to_tf32(us);
            *reinterpret_cast<uint4*>(&Bn[row][c4 * 4]) = h4_to_tf32(un);
        }
        __syncthreads();

#pragma unroll
        for (int ks8 = 0; ks8 < BK / 8; ks8++) {
            const int kb = ks8 * 8;
            uint32_t a[2][4], b[8][2];
#pragma unroll
            for (int mt = 0; mt < 2; mt++) {
                int r = wrow + mt * 16;
                a[mt][0] = Ah[r + g][kb + t];
                a[mt][1] = Ah[r + g + 8][kb + t];
                a[mt][2] = Ah[r + g][kb + t + 4];
                a[mt][3] = Ah[r + g + 8][kb + t + 4];
            }
#pragma unroll
            for (int nt = 0; nt < 8; nt++) {
                int c = wcol + nt * 8 + g;
                b[nt][0] = Bs[kb + t][c];
                b[nt][1] = Bs[kb + t + 4][c];
            }
#pragma unroll
            for (int mt = 0; mt < 2; mt++)
#pragma unroll
                for (int nt = 0; nt < 8; nt++)
                    mma_tf32(acc[mt][nt], a[mt], b[nt]);
#pragma unroll
            for (int mt = 0; mt < 2; mt++) {
                int r = wrow + mt * 16;
                a[mt][0] = Aa[r + g][kb + t];
                a[mt][1] = Aa[r + g + 8][kb + t];
                a[mt][2] = Aa[r + g][kb + t + 4];
                a[mt][3] = Aa[r + g + 8][kb + t + 4];
            }
#pragma unroll
            for (int nt = 0; nt < 8; nt++) {
                int c = wcol + nt * 8 + g;
                b[nt][0] = Bn[kb + t][c];
                b[nt][1] = Bn[kb + t + 4][c];
            }
#pragma unroll
            for (int mt = 0; mt < 2; mt++)
#pragma unroll
                for (int nt = 0; nt < 8; nt++)
                    mma_tf32(acc[mt][nt], a[mt], b[nt]);
        }
        __syncthreads();
    }

#pragma unroll
    for (int mt = 0; mt < 2; mt++) {
#pragma unroll
        for (int rr = 0; rr < 2; rr++) {
            int grow = m0 + wrow + mt * 16 + g + rr * 8;
            if (grow < nrows) {
#pragma unroll
                for (int nt = 0; nt < 8; nt++) {
                    int col = wcol + nt * 8 + t * 2;
                    size_t off = (size_t)grow * DD + col;
                    float2 res = *reinterpret_cast<const float2*>(h + off);
                    float2 bv  = *reinterpret_cast<const float2*>(bias + col);
                    float2 o;
                    o.x = acc[mt][nt][rr * 2 + 0] + bv.x + res.x;
                    o.y = acc[mt][nt][rr * 2 + 1] + bv.y + res.y;
                    *reinterpret_cast<float2*>(out + off) = o;
                }
            }
        }
    }
}

// ---------------- column stats (sum, sumsq) ----------------
__global__ __launch_bounds__(256)
void k_stats(const float* __restrict__ x, int n) {
    __shared__ float sh[8][DD];
    __shared__ float shq[8][DD];
    int lane = threadIdx.x & 31;
    int w    = threadIdx.x >> 5;
    int c    = lane * 4;
    float4 s = make_float4(0.f, 0.f, 0.f, 0.f);
    float4 q = make_float4(0.f, 0.f, 0.f, 0.f);
    for (int r = blockIdx.x * 8 + w; r < n; r += gridDim.x * 8) {
        float4 v = *reinterpret_cast<const float4*>(x + (size_t)r * DD + c);
        s.x += v.x; s.y += v.y; s.z += v.z; s.w += v.w;
        q.x += v.x * v.x; q.y += v.y * v.y; q.z += v.z * v.z; q.w += v.w * v.w;
    }
    *reinterpret_cast<float4*>(&sh[w][c])  = s;
    *reinterpret_cast<float4*>(&shq[w][c]) = q;
    __syncthreads();
    if (threadIdx.x < DD) {
        float ss = 0.f, qq = 0.f;
#pragma unroll
        for (int r = 0; r < 8; r++) { ss += sh[r][threadIdx.x]; qq += shq[r][threadIdx.x]; }
        atomicAdd(&g_stats[threadIdx.x], ss);
        atomicAdd(&g_stats[DD + threadIdx.x], qq);
    }
}

// ---------------- BN + ReLU; emits f32 h and fp16 shadow ----------------
__global__ void k_bn_relu(const float* __restrict__ hn, const float* __restrict__ gamma,
                          const float* __restrict__ beta, float* __restrict__ out, int n) {
    int idx   = blockIdx.x * blockDim.x + threadIdx.x;
    int total = n * (DD / 4);
    if (idx >= total) return;
    int c4 = idx & 31;
    int c  = c4 * 4;
    float inv = 1.0f / (float)n;

    float4 v = reinterpret_cast<const float4*>(hn)[idx];
    float4 o;
#define BN_ONE(comp, cc)                                            \
    {                                                               \
        float mu  = g_stats[cc] * inv;                              \
        float var = g_stats[DD + cc] * inv - mu * mu;               \
        float sc  = rsqrtf(var + EPS) * __ldg(gamma + cc);          \
        float sh  = __ldg(beta + cc) - mu * sc;                     \
        o.comp = fmaxf(fmaf(v.comp, sc, sh), 0.f);                  \
    }
    BN_ONE(x, c + 0)
    BN_ONE(y, c + 1)
    BN_ONE(z, c + 2)
    BN_ONE(w, c + 3)
#undef BN_ONE
    reinterpret_cast<float4*>(out)[idx] = o;
    __half2 lo = __floats2half2_rn(o.x, o.y);
    __half2 hi = __floats2half2_rn(o.z, o.w);
    uint2 u;
    u.x = *reinterpret_cast<uint32_t*>(&lo);
    u.y = *reinterpret_cast<uint32_t*>(&hi);
    reinterpret_cast<uint2*>(g_hh)[idx] = u;
}

// ---------------- launch ----------------
extern "C" void kernel_launch(void* const* d_in, const int* in_sizes, int n_in,
                              void* d_out, int out_size) {
    const float* feat   = (const float*)d_in[0];
    const int*   src    = (const int*)d_in[1];
    const int*   dst    = (const int*)d_in[2];
    const float* Wself  = (const float*)d_in[3];
    const float* Wneigh = (const float*)d_in[4];
    const float* bias   = (const float*)d_in[5];
    const float* gamma  = (const float*)d_in[6];
    const float* beta   = (const float*)d_in[7];
    float* out = (float*)d_out;

    const int N = in_sizes[0] / DD;
    const int E = in_sizes[1];

    void *p_deg, *p_stats, *p_h1, *p_h2, *p_wh;
    cudaGetSymbolAddress(&p_deg, g_deg);
    cudaGetSymbolAddress(&p_stats, g_stats);
    cudaGetSymbolAddress(&p_h1, g_h1);
    cudaGetSymbolAddress(&p_h2, g_h2);
    cudaGetSymbolAddress(&p_wh, g_wh);
    const __half* wh = (const __half*)p_wh;

    // ---- CSR build + fp16 shadows ----
    const int nb = (N + 255) / 256;
    const int feat4 = N * (DD / 4);
    const int w4    = 3 * DD * DD / 4;
    cudaMemsetAsync(p_deg, 0, (size_t)N * sizeof(int), 0);
    k_tohalf_all<<<(feat4 + 2 * w4 + 255) / 256, 256>>>(feat, Wself, Wneigh, feat4, w4);
    k_count_deg<<<(E + 255) / 256, 256>>>(dst, E);
    k_scan1<<<nb, 256>>>(N);
    k_scan3<<<nb, 256>>>(N, E);
    k_fill<<<(E + 255) / 256, 256>>>(src, dst, E);

    const int gemm_blocks   = (N + BM - 1) / BM;
    const int gather_blocks = (N + 7) / 8;
    const int bn_blocks     = (N * (DD / 4) + 255) / 256;

    const float* hcur = feat;
    for (int l = 0; l < 3; l++) {
        k_gather<<<gather_blocks, 256>>>(N);

        const __half* Wsh = wh + (size_t)l * DD * DD;
        const __half* Wnh = wh + (size_t)(3 + l) * DD * DD;
        const float*  bl  = bias + (size_t)l * DD;

        if (l < 2) {
            cudaMemsetAsync(p_stats, 0, 2 * DD * sizeof(float), 0);
            k_gemm_tc<<<gemm_blocks, 256>>>(hcur, Wsh, Wnh, bl, (float*)p_h1, N);
            k_stats<<<128, 256>>>((const float*)p_h1, N);
            k_bn_relu<<<bn_blocks, 256>>>((const float*)p_h1,
                                          gamma + (size_t)l * DD,
                                          beta + (size_t)l * DD,
                                          (float*)p_h2, N);
            hcur = (const float*)p_h2;
        } else {
            k_gemm_tc<<<gemm_blocks, 256>>>(hcur, Wsh, Wnh, bl, out, N);
        }
    }
    (void)n_in; (void)out_size;
}

// round 15
// speedup vs baseline: 1.8113x; 1.0140x over previous
#include <cuda_runtime.h>
#include <cuda_fp16.h>
#include <stdint.h>

#define NODES 50000
#define EDGES 800000
#define DD    128
#define EPS   1e-5f

// ---------------- scratch (static device globals; no allocation) ----------------
__device__ __half g_aggh[(size_t)NODES * DD]; // fp16 agg (gather output, GEMM input)
__device__ float  g_h1[(size_t)NODES * DD];   // pre-BN layer output
__device__ float  g_h2[(size_t)NODES * DD];   // post-BN layer output
__device__ __half g_hh[(size_t)NODES * DD];   // fp16 shadow of current h
__device__ __half g_wh[6 * DD * DD];          // fp16 weights TRANSPOSED [n][k]: [l]=self, [3+l]=neigh
__device__ float  g_rdeg[NODES];
__device__ int    g_deg[NODES];
__device__ int    g_csr_ptr[NODES + 1];
__device__ int    g_cursor[NODES];
__device__ int    g_csr_src[EDGES];
__device__ int    g_bsum[256];
__device__ float  g_stats[2 * DD];

// ---------------- degree + CSR build ----------------
__global__ void k_count_deg(const int* __restrict__ dst, int e) {
    int i = blockIdx.x * blockDim.x + threadIdx.x;
    if (i < e) atomicAdd(&g_deg[dst[i]], 1);
}

__global__ void k_scan1(int n) {
    __shared__ int s[256];
    int tid = threadIdx.x;
    int i = blockIdx.x * 256 + tid;
    int v = (i < n) ? g_deg[i] : 0;
    s[tid] = v;
    __syncthreads();
#pragma unroll
    for (int o = 1; o < 256; o <<= 1) {
        int x = (tid >= o) ? s[tid - o] : 0;
        __syncthreads();
        s[tid] += x;
        __syncthreads();
    }
    if (i < n) g_csr_ptr[i] = s[tid] - v;   // block-local exclusive
    if (tid == 255) g_bsum[blockIdx.x] = s[255];
}

// scan3 with inline block-offset reduction
__global__ void k_scan3(int n, int e) {
    __shared__ int s[256];
    int tid = threadIdx.x;
    int partial = 0;
    for (int j = tid; j < blockIdx.x; j += 256) partial += g_bsum[j];
    s[tid] = partial;
    __syncthreads();
#pragma unroll
    for (int o = 128; o > 0; o >>= 1) {
        if (tid < o) s[tid] += s[tid + o];
        __syncthreads();
    }
    int boff = s[0];
    int i = blockIdx.x * 256 + tid;
    if (i < n) {
        int p = g_csr_ptr[i] + boff;
        g_csr_ptr[i] = p;
        g_cursor[i] = p;
        int d = g_deg[i];
        g_rdeg[i] = 1.0f / (float)(d > 0 ? d : 1);
    }
    if (i == 0) g_csr_ptr[n] = e;
}

__global__ void k_fill(const int* __restrict__ src, const int* __restrict__ dst, int e) {
    int i = blockIdx.x * blockDim.x + threadIdx.x;
    if (i < e) {
        int pos = atomicAdd(&g_cursor[dst[i]], 1);
        g_csr_src[pos] = src[i];
    }
}

// ------- fp16 shadows: feat (direct) + weights (TRANSPOSED to [n][k]) -------------
__global__ void k_tohalf_all(const float* __restrict__ feat,
                             const float* __restrict__ Wself,
                             const float* __restrict__ Wneigh,
                             int feat4, int w4) {   // counts in float4 units
    int idx = blockIdx.x * blockDim.x + threadIdx.x;
    if (idx < feat4) {
        float4 v = reinterpret_cast<const float4*>(feat)[idx];
        __half2 lo = __floats2half2_rn(v.x, v.y);
        __half2 hi = __floats2half2_rn(v.z, v.w);
        uint2 u;
        u.x = *reinterpret_cast<uint32_t*>(&lo);
        u.y = *reinterpret_cast<uint32_t*>(&hi);
        reinterpret_cast<uint2*>(g_hh)[idx] = u;
    } else if (idx < feat4 + 2 * w4) {
        int k4 = idx - feat4;
        const float* srcp = (k4 < w4) ? Wself : Wneigh;
        int j = (k4 < w4) ? k4 : k4 - w4;            // float4 index within 3*DD*DD tensor
        __half* dstp = g_wh + ((k4 < w4) ? 0 : 3 * DD * DD);
        int l  = j / (DD * DD / 4);
        int r  = j % (DD * DD / 4);
        int kk = r / (DD / 4);                       // source row (k)
        int n0 = (r % (DD / 4)) * 4;                 // source col base (n)
        float4 v = reinterpret_cast<const float4*>(srcp)[j];
        __half* base = dstp + (size_t)l * DD * DD;
        base[(n0 + 0) * DD + kk] = __float2half_rn(v.x);
        base[(n0 + 1) * DD + kk] = __float2half_rn(v.y);
        base[(n0 + 2) * DD + kk] = __float2half_rn(v.z);
        base[(n0 + 3) * DD + kk] = __float2half_rn(v.w);
    }
}

// ---------------- gather: one warp per dst node, fp16 rows, fp16 agg out ----------
__global__ __launch_bounds__(256)
void k_gather(int n) {
    int node = (blockIdx.x * blockDim.x + threadIdx.x) >> 5;
    int lane = threadIdx.x & 31;
    if (node >= n) return;
    const __half* hh = g_hh;
    int beg = g_csr_ptr[node];
    int end = g_csr_ptr[node + 1];
    float4 acc = make_float4(0.f, 0.f, 0.f, 0.f);
    for (int base = beg; base < end; base += 32) {
        int mye  = base + lane;
        int sidx = (mye < end) ? g_csr_src[mye] : 0;
        int cnt  = min(32, end - base);
        int j = 0;
        for (; j + 3 < cnt; j += 4) {
            int s0 = __shfl_sync(0xffffffffu, sidx, j);
            int s1 = __shfl_sync(0xffffffffu, sidx, j + 1);
            int s2 = __shfl_sync(0xffffffffu, sidx, j + 2);
            int s3 = __shfl_sync(0xffffffffu, sidx, j + 3);
            uint2 u0 = *reinterpret_cast<const uint2*>(hh + (size_t)s0 * DD + lane * 4);
            uint2 u1 = *reinterpret_cast<const uint2*>(hh + (size_t)s1 * DD + lane * 4);
            uint2 u2 = *reinterpret_cast<const uint2*>(hh + (size_t)s2 * DD + lane * 4);
            uint2 u3 = *reinterpret_cast<const uint2*>(hh + (size_t)s3 * DD + lane * 4);
            float2 a0 = __half22float2(*reinterpret_cast<__half2*>(&u0.x));
            float2 b0 = __half22float2(*reinterpret_cast<__half2*>(&u0.y));
            float2 a1 = __half22float2(*reinterpret_cast<__half2*>(&u1.x));
            float2 b1 = __half22float2(*reinterpret_cast<__half2*>(&u1.y));
            float2 a2 = __half22float2(*reinterpret_cast<__half2*>(&u2.x));
            float2 b2 = __half22float2(*reinterpret_cast<__half2*>(&u2.y));
            float2 a3 = __half22float2(*reinterpret_cast<__half2*>(&u3.x));
            float2 b3 = __half22float2(*reinterpret_cast<__half2*>(&u3.y));
            acc.x += a0.x + a1.x + a2.x + a3.x;
            acc.y += a0.y + a1.y + a2.y + a3.y;
            acc.z += b0.x + b1.x + b2.x + b3.x;
            acc.w += b0.y + b1.y + b2.y + b3.y;
        }
        for (; j < cnt; j++) {
            int s0 = __shfl_sync(0xffffffffu, sidx, j);
            uint2 u0 = *reinterpret_cast<const uint2*>(hh + (size_t)s0 * DD + lane * 4);
            float2 a0 = __half22float2(*reinterpret_cast<__half2*>(&u0.x));
            float2 b0 = __half22float2(*reinterpret_cast<__half2*>(&u0.y));
            acc.x += a0.x; acc.y += a0.y; acc.z += b0.x; acc.w += b0.y;
        }
    }
    float rd = g_rdeg[node];
    __half2 lo = __floats2half2_rn(acc.x * rd, acc.y * rd);
    __half2 hi = __floats2half2_rn(acc.z * rd, acc.w * rd);
    uint2 u;
    u.x = *reinterpret_cast<uint32_t*>(&lo);
    u.y = *reinterpret_cast<uint32_t*>(&hi);
    *reinterpret_cast<uint2*>(g_aggh + (size_t)node * DD + lane * 4) = u;
}

// ---------------- fp16 tensor-core dual GEMM + bias + residual --------------------
__device__ __forceinline__ void mma_f16(float* d, const uint32_t* a, const uint32_t* b) {
    asm volatile(
        "mma.sync.aligned.m16n8k16.row.col.f32.f16.f16.f32 "
        "{%0,%1,%2,%3}, {%4,%5,%6,%7}, {%8,%9}, {%0,%1,%2,%3};\n"
        : "+f"(d[0]), "+f"(d[1]), "+f"(d[2]), "+f"(d[3])
        : "r"(a[0]), "r"(a[1]), "r"(a[2]), "r"(a[3]), "r"(b[0]), "r"(b[1]));
}

#define BM 128
#define BK 16
#define T_STRIDE 10   // 8 half2-words per row + 2 pad

// A tiles [row][k] fp16 (half2-packed along k); B tiles [n][k] fp16 (from W^T).
__global__ __launch_bounds__(256, 2)
void k_gemm_tc(const float* __restrict__ h,
               const __half* __restrict__ Wsh, const __half* __restrict__ Wnh,
               const float* __restrict__ bias, float* __restrict__ out, int nrows) {
    __shared__ uint32_t Ah[128][T_STRIDE];
    __shared__ uint32_t Aa[128][T_STRIDE];
    __shared__ uint32_t Bs[128][T_STRIDE];
    __shared__ uint32_t Bn[128][T_STRIDE];

    const int tid  = threadIdx.x;
    const int warp = tid >> 5;
    const int lane = tid & 31;
    const int g    = lane >> 2;
    const int t    = lane & 3;
    const int wm   = warp & 3;
    const int wn   = warp >> 2;
    const int m0   = blockIdx.x * BM;
    const int wrow = wm * 32;
    const int wcol = wn * 64;

    float acc[2][8][4];
#pragma unroll
    for (int mt = 0; mt < 2; mt++)
#pragma unroll
        for (int nt = 0; nt < 8; nt++)
#pragma unroll
            for (int j = 0; j < 4; j++) acc[mt][nt][j] = 0.f;

    for (int kc = 0; kc < DD / BK; kc++) {
        const int ks = kc * BK;
        // A tiles: 128 rows x 16 halves = 512 uint2; 2 per thread per matrix
#pragma unroll
        for (int r = 0; r < 2; r++) {
            int id  = tid + r * 256;          // 0..511
            int row = id >> 2;                // 0..127
            int q   = id & 3;                 // 0..3 (uint2 within row)
            int grow = m0 + row;
            uint2 uh = make_uint2(0u, 0u);
            uint2 ua = make_uint2(0u, 0u);
            if (grow < nrows) {
                size_t off = (size_t)grow * DD + ks + q * 4;
                uh = *reinterpret_cast<const uint2*>(g_hh + off);
                ua = *reinterpret_cast<const uint2*>(g_aggh + off);
            }
            *reinterpret_cast<uint2*>(&Ah[row][q * 2]) = uh;
            *reinterpret_cast<uint2*>(&Aa[row][q * 2]) = ua;
        }
        // B tiles from W^T [n][k]: 128 n x 16 halves = 512 uint2; 2 per thread per matrix
#pragma unroll
        for (int r = 0; r < 2; r++) {
            int id  = tid + r * 256;
            int row = id >> 2;                // n
            int q   = id & 3;
            size_t off = (size_t)row * DD + ks + q * 4;
            uint2 us = *reinterpret_cast<const uint2*>(Wsh + off);
            uint2 un = *reinterpret_cast<const uint2*>(Wnh + off);
            *reinterpret_cast<uint2*>(&Bs[row][q * 2]) = us;
            *reinterpret_cast<uint2*>(&Bn[row][q * 2]) = un;
        }
        __syncthreads();

        // one m16n8k16 per (term, mt, nt)
        uint32_t a[2][4], b[8][2];
#pragma unroll
        for (int mt = 0; mt < 2; mt++) {
            int r = wrow + mt * 16;
            a[mt][0] = Ah[r + g][t];
            a[mt][1] = Ah[r + g + 8][t];
            a[mt][2] = Ah[r + g][t + 4];
            a[mt][3] = Ah[r + g + 8][t + 4];
        }
#pragma unroll
        for (int nt = 0; nt < 8; nt++) {
            int c = wcol + nt * 8 + g;
            b[nt][0] = Bs[c][t];
            b[nt][1] = Bs[c][t + 4];
        }
#pragma unroll
        for (int mt = 0; mt < 2; mt++)
#pragma unroll
            for (int nt = 0; nt < 8; nt++)
                mma_f16(acc[mt][nt], a[mt], b[nt]);
#pragma unroll
        for (int mt = 0; mt < 2; mt++) {
            int r = wrow + mt * 16;
            a[mt][0] = Aa[r + g][t];
            a[mt][1] = Aa[r + g + 8][t];
            a[mt][2] = Aa[r + g][t + 4];
            a[mt][3] = Aa[r + g + 8][t + 4];
        }
#pragma unroll
        for (int nt = 0; nt < 8; nt++) {
            int c = wcol + nt * 8 + g;
            b[nt][0] = Bn[c][t];
            b[nt][1] = Bn[c][t + 4];
        }
#pragma unroll
        for (int mt = 0; mt < 2; mt++)
#pragma unroll
            for (int nt = 0; nt < 8; nt++)
                mma_f16(acc[mt][nt], a[mt], b[nt]);
        __syncthreads();
    }

#pragma unroll
    for (int mt = 0; mt < 2; mt++) {
#pragma unroll
        for (int rr = 0; rr < 2; rr++) {
            int grow = m0 + wrow + mt * 16 + g + rr * 8;
            if (grow < nrows) {
#pragma unroll
                for (int nt = 0; nt < 8; nt++) {
                    int col = wcol + nt * 8 + t * 2;
                    size_t off = (size_t)grow * DD + col;
                    float2 res = *reinterpret_cast<const float2*>(h + off);
                    float2 bv  = *reinterpret_cast<const float2*>(bias + col);
                    float2 o;
                    o.x = acc[mt][nt][rr * 2 + 0] + bv.x + res.x;
                    o.y = acc[mt][nt][rr * 2 + 1] + bv.y + res.y;
                    *reinterpret_cast<float2*>(out + off) = o;
                }
            }
        }
    }
}

// ---------------- column stats (sum, sumsq) ----------------
__global__ __launch_bounds__(256)
void k_stats(const float* __restrict__ x, int n) {
    __shared__ float sh[8][DD];
    __shared__ float shq[8][DD];
    int lane = threadIdx.x & 31;
    int w    = threadIdx.x >> 5;
    int c    = lane * 4;
    float4 s = make_float4(0.f, 0.f, 0.f, 0.f);
    float4 q = make_float4(0.f, 0.f, 0.f, 0.f);
    for (int r = blockIdx.x * 8 + w; r < n; r += gridDim.x * 8) {
        float4 v = *reinterpret_cast<const float4*>(x + (size_t)r * DD + c);
        s.x += v.x; s.y += v.y; s.z += v.z; s.w += v.w;
        q.x += v.x * v.x; q.y += v.y * v.y; q.z += v.z * v.z; q.w += v.w * v.w;
    }
    *reinterpret_cast<float4*>(&sh[w][c])  = s;
    *reinterpret_cast<float4*>(&shq[w][c]) = q;
    __syncthreads();
    if (threadIdx.x < DD) {
        float ss = 0.f, qq = 0.f;
#pragma unroll
        for (int r = 0; r < 8; r++) { ss += sh[r][threadIdx.x]; qq += shq[r][threadIdx.x]; }
        atomicAdd(&g_stats[threadIdx.x], ss);
        atomicAdd(&g_stats[DD + threadIdx.x], qq);
    }
}

// ---------------- BN + ReLU; emits f32 h and fp16 shadow ----------------
__global__ void k_bn_relu(const float* __restrict__ hn, const float* __restrict__ gamma,
                          const float* __restrict__ beta, float* __restrict__ out, int n) {
    int idx   = blockIdx.x * blockDim.x + threadIdx.x;
    int total = n * (DD / 4);
    if (idx >= total) return;
    int c4 = idx & 31;
    int c  = c4 * 4;
    float inv = 1.0f / (float)n;

    float4 v = reinterpret_cast<const float4*>(hn)[idx];
    float4 o;
#define BN_ONE(comp, cc)                                            \
    {                                                               \
        float mu  = g_stats[cc] * inv;                              \
        float var = g_stats[DD + cc] * inv - mu * mu;               \
        float sc  = rsqrtf(var + EPS) * __ldg(gamma + cc);          \
        float sh  = __ldg(beta + cc) - mu * sc;                     \
        o.comp = fmaxf(fmaf(v.comp, sc, sh), 0.f);                  \
    }
    BN_ONE(x, c + 0)
    BN_ONE(y, c + 1)
    BN_ONE(z, c + 2)
    BN_ONE(w, c + 3)
#undef BN_ONE
    reinterpret_cast<float4*>(out)[idx] = o;
    __half2 lo = __floats2half2_rn(o.x, o.y);
    __half2 hi = __floats2half2_rn(o.z, o.w);
    uint2 u;
    u.x = *reinterpret_cast<uint32_t*>(&lo);
    u.y = *reinterpret_cast<uint32_t*>(&hi);
    reinterpret_cast<uint2*>(g_hh)[idx] = u;
}

// ---------------- launch ----------------
extern "C" void kernel_launch(void* const* d_in, const int* in_sizes, int n_in,
                              void* d_out, int out_size) {
    const float* feat   = (const float*)d_in[0];
    const int*   src    = (const int*)d_in[1];
    const int*   dst    = (const int*)d_in[2];
    const float* Wself  = (const float*)d_in[3];
    const float* Wneigh = (const float*)d_in[4];
    const float* bias   = (const float*)d_in[5];
    const float* gamma  = (const float*)d_in[6];
    const float* beta   = (const float*)d_in[7];
    float* out = (float*)d_out;

    const int N = in_sizes[0] / DD;
    const int E = in_sizes[1];

    void *p_deg, *p_stats, *p_h1, *p_h2, *p_wh;
    cudaGetSymbolAddress(&p_deg, g_deg);
    cudaGetSymbolAddress(&p_stats, g_stats);
    cudaGetSymbolAddress(&p_h1, g_h1);
    cudaGetSymbolAddress(&p_h2, g_h2);
    cudaGetSymbolAddress(&p_wh, g_wh);
    const __half* wh = (const __half*)p_wh;

    // ---- CSR build + fp16 shadows ----
    const int nb = (N + 255) / 256;
    const int feat4 = N * (DD / 4);
    const int w4    = 3 * DD * DD / 4;
    cudaMemsetAsync(p_deg, 0, (size_t)N * sizeof(int), 0);
    k_tohalf_all<<<(feat4 + 2 * w4 + 255) / 256, 256>>>(feat, Wself, Wneigh, feat4, w4);
    k_count_deg<<<(E + 255) / 256, 256>>>(dst, E);
    k_scan1<<<nb, 256>>>(N);
    k_scan3<<<nb, 256>>>(N, E);
    k_fill<<<(E + 255) / 256, 256>>>(src, dst, E);

    const int gemm_blocks   = (N + BM - 1) / BM;
    const int gather_blocks = (N + 7) / 8;
    const int bn_blocks     = (N * (DD / 4) + 255) / 256;

    const float* hcur = feat;
    for (int l = 0; l < 3; l++) {
        k_gather<<<gather_blocks, 256>>>(N);

        const __half* Wsh = wh + (size_t)l * DD * DD;
        const __half* Wnh = wh + (size_t)(3 + l) * DD * DD;
        const float*  bl  = bias + (size_t)l * DD;

        if (l < 2) {
            cudaMemsetAsync(p_stats, 0, 2 * DD * sizeof(float), 0);
            k_gemm_tc<<<gemm_blocks, 256>>>(hcur, Wsh, Wnh, bl, (float*)p_h1, N);
            k_stats<<<128, 256>>>((const float*)p_h1, N);
            k_bn_relu<<<bn_blocks, 256>>>((const float*)p_h1,
                                          gamma + (size_t)l * DD,
                                          beta + (size_t)l * DD,
                                          (float*)p_h2, N);
            hcur = (const float*)p_h2;
        } else {
            k_gemm_tc<<<gemm_blocks, 256>>>(hcur, Wsh, Wnh, bl, out, N);
        }
    }
    (void)n_in; (void)out_size;
}

// round 16
// speedup vs baseline: 1.8551x; 1.0242x over previous
#include <cuda_runtime.h>
#include <cuda_fp16.h>
#include <stdint.h>

#define NODES 50000
#define EDGES 800000
#define DD    128
#define EPS   1e-5f

// ---------------- scratch (static device globals; no allocation) ----------------
__device__ __half g_aggh[(size_t)NODES * DD]; // fp16 agg (gather output, GEMM input)
__device__ float  g_h1[(size_t)NODES * DD];   // pre-BN layer output (f32, for stats/BN)
__device__ __half g_hh[(size_t)NODES * DD];   // fp16 shadow of current h (gather+GEMM+residual)
__device__ __half g_wh[6 * DD * DD];          // fp16 weights TRANSPOSED [n][k]: [l]=self, [3+l]=neigh
__device__ float  g_rdeg[NODES];
__device__ int    g_deg[NODES];
__device__ int    g_csr_ptr[NODES + 1];
__device__ int    g_cursor[NODES];
__device__ int    g_csr_src[EDGES];
__device__ int    g_bsum[256];
__device__ float  g_stats[2 * DD];

// ---------------- degree + CSR build ----------------
__global__ void k_count_deg(const int* __restrict__ dst, int e) {
    int i = blockIdx.x * blockDim.x + threadIdx.x;
    if (i < e) atomicAdd(&g_deg[dst[i]], 1);
}

__global__ void k_scan1(int n) {
    __shared__ int s[256];
    int tid = threadIdx.x;
    int i = blockIdx.x * 256 + tid;
    int v = (i < n) ? g_deg[i] : 0;
    s[tid] = v;
    __syncthreads();
#pragma unroll
    for (int o = 1; o < 256; o <<= 1) {
        int x = (tid >= o) ? s[tid - o] : 0;
        __syncthreads();
        s[tid] += x;
        __syncthreads();
    }
    if (i < n) g_csr_ptr[i] = s[tid] - v;   // block-local exclusive
    if (tid == 255) g_bsum[blockIdx.x] = s[255];
}

// scan3 with inline block-offset reduction
__global__ void k_scan3(int n, int e) {
    __shared__ int s[256];
    int tid = threadIdx.x;
    int partial = 0;
    for (int j = tid; j < blockIdx.x; j += 256) partial += g_bsum[j];
    s[tid] = partial;
    __syncthreads();
#pragma unroll
    for (int o = 128; o > 0; o >>= 1) {
        if (tid < o) s[tid] += s[tid + o];
        __syncthreads();
    }
    int boff = s[0];
    int i = blockIdx.x * 256 + tid;
    if (i < n) {
        int p = g_csr_ptr[i] + boff;
        g_csr_ptr[i] = p;
        g_cursor[i] = p;
        int d = g_deg[i];
        g_rdeg[i] = 1.0f / (float)(d > 0 ? d : 1);
    }
    if (i == 0) g_csr_ptr[n] = e;
}

__global__ void k_fill(const int* __restrict__ src, const int* __restrict__ dst, int e) {
    int i = blockIdx.x * blockDim.x + threadIdx.x;
    if (i < e) {
        int pos = atomicAdd(&g_cursor[dst[i]], 1);
        g_csr_src[pos] = src[i];
    }
}

// ------- fp16 shadows: feat (direct) + weights (TRANSPOSED to [n][k]) -------------
__global__ void k_tohalf_all(const float* __restrict__ feat,
                             const float* __restrict__ Wself,
                             const float* __restrict__ Wneigh,
                             int feat4, int w4) {   // counts in float4 units
    int idx = blockIdx.x * blockDim.x + threadIdx.x;
    if (idx < feat4) {
        float4 v = reinterpret_cast<const float4*>(feat)[idx];
        __half2 lo = __floats2half2_rn(v.x, v.y);
        __half2 hi = __floats2half2_rn(v.z, v.w);
        uint2 u;
        u.x = *reinterpret_cast<uint32_t*>(&lo);
        u.y = *reinterpret_cast<uint32_t*>(&hi);
        reinterpret_cast<uint2*>(g_hh)[idx] = u;
    } else if (idx < feat4 + 2 * w4) {
        int k4 = idx - feat4;
        const float* srcp = (k4 < w4) ? Wself : Wneigh;
        int j = (k4 < w4) ? k4 : k4 - w4;            // float4 index within 3*DD*DD tensor
        __half* dstp = g_wh + ((k4 < w4) ? 0 : 3 * DD * DD);
        int l  = j / (DD * DD / 4);
        int r  = j % (DD * DD / 4);
        int kk = r / (DD / 4);                       // source row (k)
        int n0 = (r % (DD / 4)) * 4;                 // source col base (n)
        float4 v = reinterpret_cast<const float4*>(srcp)[j];
        __half* base = dstp + (size_t)l * DD * DD;
        base[(n0 + 0) * DD + kk] = __float2half_rn(v.x);
        base[(n0 + 1) * DD + kk] = __float2half_rn(v.y);
        base[(n0 + 2) * DD + kk] = __float2half_rn(v.z);
        base[(n0 + 3) * DD + kk] = __float2half_rn(v.w);
    }
}

// ---------------- gather: one warp per dst node, fp16 rows, fp16 agg out ----------
__global__ __launch_bounds__(256)
void k_gather(int n) {
    int node = (blockIdx.x * blockDim.x + threadIdx.x) >> 5;
    int lane = threadIdx.x & 31;
    if (node >= n) return;
    const __half* hh = g_hh;
    int beg = g_csr_ptr[node];
    int end = g_csr_ptr[node + 1];
    float4 acc = make_float4(0.f, 0.f, 0.f, 0.f);
    for (int base = beg; base < end; base += 32) {
        int mye  = base + lane;
        int sidx = (mye < end) ? g_csr_src[mye] : 0;
        int cnt  = min(32, end - base);
        int j = 0;
        // 8-deep unroll: keep 8 independent row loads in flight
        for (; j + 7 < cnt; j += 8) {
            int  ss[8];
            uint2 uu[8];
#pragma unroll
            for (int q = 0; q < 8; q++)
                ss[q] = __shfl_sync(0xffffffffu, sidx, j + q);
#pragma unroll
            for (int q = 0; q < 8; q++)
                uu[q] = *reinterpret_cast<const uint2*>(hh + (size_t)ss[q] * DD + lane * 4);
#pragma unroll
            for (int q = 0; q < 8; q++) {
                float2 a = __half22float2(*reinterpret_cast<__half2*>(&uu[q].x));
                float2 b = __half22float2(*reinterpret_cast<__half2*>(&uu[q].y));
                acc.x += a.x; acc.y += a.y; acc.z += b.x; acc.w += b.y;
            }
        }
        for (; j < cnt; j++) {
            int s0 = __shfl_sync(0xffffffffu, sidx, j);
            uint2 u0 = *reinterpret_cast<const uint2*>(hh + (size_t)s0 * DD + lane * 4);
            float2 a0 = __half22float2(*reinterpret_cast<__half2*>(&u0.x));
            float2 b0 = __half22float2(*reinterpret_cast<__half2*>(&u0.y));
            acc.x += a0.x; acc.y += a0.y; acc.z += b0.x; acc.w += b0.y;
        }
    }
    float rd = g_rdeg[node];
    __half2 lo = __floats2half2_rn(acc.x * rd, acc.y * rd);
    __half2 hi = __floats2half2_rn(acc.z * rd, acc.w * rd);
    uint2 u;
    u.x = *reinterpret_cast<uint32_t*>(&lo);
    u.y = *reinterpret_cast<uint32_t*>(&hi);
    *reinterpret_cast<uint2*>(g_aggh + (size_t)node * DD + lane * 4) = u;
}

// ---------------- fp16 tensor-core dual GEMM + bias + residual(fp16) --------------
__device__ __forceinline__ void mma_f16(float* d, const uint32_t* a, const uint32_t* b) {
    asm volatile(
        "mma.sync.aligned.m16n8k16.row.col.f32.f16.f16.f32 "
        "{%0,%1,%2,%3}, {%4,%5,%6,%7}, {%8,%9}, {%0,%1,%2,%3};\n"
        : "+f"(d[0]), "+f"(d[1]), "+f"(d[2]), "+f"(d[3])
        : "r"(a[0]), "r"(a[1]), "r"(a[2]), "r"(a[3]), "r"(b[0]), "r"(b[1]));
}

#define BM 128
#define BK 16
#define T_STRIDE 10   // 8 half2-words per row + 2 pad

// A tiles [row][k] fp16; B tiles [n][k] fp16 (from W^T); residual from g_hh (fp16).
__global__ __launch_bounds__(256, 2)
void k_gemm_tc(const __half* __restrict__ Wsh, const __half* __restrict__ Wnh,
               const float* __restrict__ bias, float* __restrict__ out, int nrows) {
    __shared__ uint32_t Ah[128][T_STRIDE];
    __shared__ uint32_t Aa[128][T_STRIDE];
    __shared__ uint32_t Bs[128][T_STRIDE];
    __shared__ uint32_t Bn[128][T_STRIDE];

    const int tid  = threadIdx.x;
    const int warp = tid >> 5;
    const int lane = tid & 31;
    const int g    = lane >> 2;
    const int t    = lane & 3;
    const int wm   = warp & 3;
    const int wn   = warp >> 2;
    const int m0   = blockIdx.x * BM;
    const int wrow = wm * 32;
    const int wcol = wn * 64;

    float acc[2][8][4];
#pragma unroll
    for (int mt = 0; mt < 2; mt++)
#pragma unroll
        for (int nt = 0; nt < 8; nt++)
#pragma unroll
            for (int j = 0; j < 4; j++) acc[mt][nt][j] = 0.f;

    for (int kc = 0; kc < DD / BK; kc++) {
        const int ks = kc * BK;
        // A tiles: 128 rows x 16 halves = 512 uint2; 2 per thread per matrix
#pragma unroll
        for (int r = 0; r < 2; r++) {
            int id  = tid + r * 256;          // 0..511
            int row = id >> 2;                // 0..127
            int q   = id & 3;                 // 0..3 (uint2 within row)
            int grow = m0 + row;
            uint2 uh = make_uint2(0u, 0u);
            uint2 ua = make_uint2(0u, 0u);
            if (grow < nrows) {
                size_t off = (size_t)grow * DD + ks + q * 4;
                uh = *reinterpret_cast<const uint2*>(g_hh + off);
                ua = *reinterpret_cast<const uint2*>(g_aggh + off);
            }
            *reinterpret_cast<uint2*>(&Ah[row][q * 2]) = uh;
            *reinterpret_cast<uint2*>(&Aa[row][q * 2]) = ua;
        }
        // B tiles from W^T [n][k]
#pragma unroll
        for (int r = 0; r < 2; r++) {
            int id  = tid + r * 256;
            int row = id >> 2;                // n
            int q   = id & 3;
            size_t off = (size_t)row * DD + ks + q * 4;
            uint2 us = *reinterpret_cast<const uint2*>(Wsh + off);
            uint2 un = *reinterpret_cast<const uint2*>(Wnh + off);
            *reinterpret_cast<uint2*>(&Bs[row][q * 2]) = us;
            *reinterpret_cast<uint2*>(&Bn[row][q * 2]) = un;
        }
        __syncthreads();

        uint32_t a[2][4], b[8][2];
#pragma unroll
        for (int mt = 0; mt < 2; mt++) {
            int r = wrow + mt * 16;
            a[mt][0] = Ah[r + g][t];
            a[mt][1] = Ah[r + g + 8][t];
            a[mt][2] = Ah[r + g][t + 4];
            a[mt][3] = Ah[r + g + 8][t + 4];
        }
#pragma unroll
        for (int nt = 0; nt < 8; nt++) {
            int c = wcol + nt * 8 + g;
            b[nt][0] = Bs[c][t];
            b[nt][1] = Bs[c][t + 4];
        }
#pragma unroll
        for (int mt = 0; mt < 2; mt++)
#pragma unroll
            for (int nt = 0; nt < 8; nt++)
                mma_f16(acc[mt][nt], a[mt], b[nt]);
#pragma unroll
        for (int mt = 0; mt < 2; mt++) {
            int r = wrow + mt * 16;
            a[mt][0] = Aa[r + g][t];
            a[mt][1] = Aa[r + g + 8][t];
            a[mt][2] = Aa[r + g][t + 4];
            a[mt][3] = Aa[r + g + 8][t + 4];
        }
#pragma unroll
        for (int nt = 0; nt < 8; nt++) {
            int c = wcol + nt * 8 + g;
            b[nt][0] = Bn[c][t];
            b[nt][1] = Bn[c][t + 4];
        }
#pragma unroll
        for (int mt = 0; mt < 2; mt++)
#pragma unroll
            for (int nt = 0; nt < 8; nt++)
                mma_f16(acc[mt][nt], a[mt], b[nt]);
        __syncthreads();
    }

    // epilogue: + bias + residual (fp16 shadow), write f32 out
#pragma unroll
    for (int mt = 0; mt < 2; mt++) {
#pragma unroll
        for (int rr = 0; rr < 2; rr++) {
            int grow = m0 + wrow + mt * 16 + g + rr * 8;
            if (grow < nrows) {
#pragma unroll
                for (int nt = 0; nt < 8; nt++) {
                    int col = wcol + nt * 8 + t * 2;
                    size_t off = (size_t)grow * DD + col;
                    __half2 rh = *reinterpret_cast<const __half2*>(g_hh + off);
                    float2 res = __half22float2(rh);
                    float2 bv  = *reinterpret_cast<const float2*>(bias + col);
                    float2 o;
                    o.x = acc[mt][nt][rr * 2 + 0] + bv.x + res.x;
                    o.y = acc[mt][nt][rr * 2 + 1] + bv.y + res.y;
                    *reinterpret_cast<float2*>(out + off) = o;
                }
            }
        }
    }
}

// ---------------- column stats (sum, sumsq) ----------------
__global__ __launch_bounds__(256)
void k_stats(const float* __restrict__ x, int n) {
    __shared__ float sh[8][DD];
    __shared__ float shq[8][DD];
    int lane = threadIdx.x & 31;
    int w    = threadIdx.x >> 5;
    int c    = lane * 4;
    float4 s = make_float4(0.f, 0.f, 0.f, 0.f);
    float4 q = make_float4(0.f, 0.f, 0.f, 0.f);
    for (int r = blockIdx.x * 8 + w; r < n; r += gridDim.x * 8) {
        float4 v = *reinterpret_cast<const float4*>(x + (size_t)r * DD + c);
        s.x += v.x; s.y += v.y; s.z += v.z; s.w += v.w;
        q.x += v.x * v.x; q.y += v.y * v.y; q.z += v.z * v.z; q.w += v.w * v.w;
    }
    *reinterpret_cast<float4*>(&sh[w][c])  = s;
    *reinterpret_cast<float4*>(&shq[w][c]) = q;
    __syncthreads();
    if (threadIdx.x < DD) {
        float ss = 0.f, qq = 0.f;
#pragma unroll
        for (int r = 0; r < 8; r++) { ss += sh[r][threadIdx.x]; qq += shq[r][threadIdx.x]; }
        atomicAdd(&g_stats[threadIdx.x], ss);
        atomicAdd(&g_stats[DD + threadIdx.x], qq);
    }
}

// ---------------- BN + ReLU; emits ONLY fp16 shadow ----------------
__global__ void k_bn_relu(const float* __restrict__ hn, const float* __restrict__ gamma,
                          const float* __restrict__ beta, int n) {
    int idx   = blockIdx.x * blockDim.x + threadIdx.x;
    int total = n * (DD / 4);
    if (idx >= total) return;
    int c4 = idx & 31;
    int c  = c4 * 4;
    float inv = 1.0f / (float)n;

    float4 v = reinterpret_cast<const float4*>(hn)[idx];
    float4 o;
#define BN_ONE(comp, cc)                                            \
    {                                                               \
        float mu  = g_stats[cc] * inv;                              \
        float var = g_stats[DD + cc] * inv - mu * mu;               \
        float sc  = rsqrtf(var + EPS) * __ldg(gamma + cc);          \
        float sh  = __ldg(beta + cc) - mu * sc;                     \
        o.comp = fmaxf(fmaf(v.comp, sc, sh), 0.f);                  \
    }
    BN_ONE(x, c + 0)
    BN_ONE(y, c + 1)
    BN_ONE(z, c + 2)
    BN_ONE(w, c + 3)
#undef BN_ONE
    __half2 lo = __floats2half2_rn(o.x, o.y);
    __half2 hi = __floats2half2_rn(o.z, o.w);
    uint2 u;
    u.x = *reinterpret_cast<uint32_t*>(&lo);
    u.y = *reinterpret_cast<uint32_t*>(&hi);
    reinterpret_cast<uint2*>(g_hh)[idx] = u;
}

// ---------------- launch ----------------
extern "C" void kernel_launch(void* const* d_in, const int* in_sizes, int n_in,
                              void* d_out, int out_size) {
    const float* feat   = (const float*)d_in[0];
    const int*   src    = (const int*)d_in[1];
    const int*   dst    = (const int*)d_in[2];
    const float* Wself  = (const float*)d_in[3];
    const float* Wneigh = (const float*)d_in[4];
    const float* bias   = (const float*)d_in[5];
    const float* gamma  = (const float*)d_in[6];
    const float* beta   = (const float*)d_in[7];
    float* out = (float*)d_out;

    const int N = in_sizes[0] / DD;
    const int E = in_sizes[1];

    void *p_deg, *p_stats, *p_h1, *p_wh;
    cudaGetSymbolAddress(&p_deg, g_deg);
    cudaGetSymbolAddress(&p_stats, g_stats);
    cudaGetSymbolAddress(&p_h1, g_h1);
    cudaGetSymbolAddress(&p_wh, g_wh);
    const __half* wh = (const __half*)p_wh;

    // ---- CSR build + fp16 shadows ----
    const int nb = (N + 255) / 256;
    const int feat4 = N * (DD / 4);
    const int w4    = 3 * DD * DD / 4;
    cudaMemsetAsync(p_deg, 0, (size_t)N * sizeof(int), 0);
    k_tohalf_all<<<(feat4 + 2 * w4 + 255) / 256, 256>>>(feat, Wself, Wneigh, feat4, w4);
    k_count_deg<<<(E + 255) / 256, 256>>>(dst, E);
    k_scan1<<<nb, 256>>>(N);
    k_scan3<<<nb, 256>>>(N, E);
    k_fill<<<(E + 255) / 256, 256>>>(src, dst, E);

    const int gemm_blocks   = (N + BM - 1) / BM;
    const int gather_blocks = (N + 7) / 8;
    const int bn_blocks     = (N * (DD / 4) + 255) / 256;

    for (int l = 0; l < 3; l++) {
        k_gather<<<gather_blocks, 256>>>(N);

        const __half* Wsh = wh + (size_t)l * DD * DD;
        const __half* Wnh = wh + (size_t)(3 + l) * DD * DD;
        const float*  bl  = bias + (size_t)l * DD;

        if (l < 2) {
            cudaMemsetAsync(p_stats, 0, 2 * DD * sizeof(float), 0);
            k_gemm_tc<<<gemm_blocks, 256>>>(Wsh, Wnh, bl, (float*)p_h1, N);
            k_stats<<<128, 256>>>((const float*)p_h1, N);
            k_bn_relu<<<bn_blocks, 256>>>((const float*)p_h1,
                                          gamma + (size_t)l * DD,
                                          beta + (size_t)l * DD, N);
        } else {
            k_gemm_tc<<<gemm_blocks, 256>>>(Wsh, Wnh, bl, out, N);
        }
    }
    (void)n_in; (void)out_size;
}